// round 2
// baseline (speedup 1.0000x reference)
#include <cuda_runtime.h>
#include <math.h>

#define BB 8
#define CC 64
#define HH 256
#define WW 256
#define OHH 131
#define OWW 131
#define PP (OHH*OWW)      /* 17161 */
#define PSTR 17164        /* padded channel stride (multiple of 4 for float4) */
#define HWSZ (HH*WW)      /* 65536 */

// db4 filters
__constant__ float DEC_LO[8] = {
    -0.010597401784997278f, 0.032883011666982945f, 0.030841381835986965f,
    -0.18703481171888114f, -0.02798376941698385f, 0.6308807679295904f,
    0.7148465705525415f, 0.23037781330885523f };
__constant__ float DEC_HI[8] = {
    -0.23037781330885523f, 0.7148465705525415f, -0.6308807679295904f,
    -0.02798376941698385f, 0.18703481171888114f, 0.030841381835986965f,
    -0.032883011666982945f, -0.010597401784997278f };

// Scratch (device globals; allocation-free rule)
__device__ float g_ff[(size_t)BB*256*PSTR];    // ff then gated coeffs, (b, q=k*64+c, p)
__device__ float g_z[(size_t)BB*128*PSTR];     // z pre-GN, (b, o, p)
__device__ float g_recon[(size_t)BB*64*HWSZ];  // (b, c, h, w)
__device__ float g_stats[128];                 // (b,g): sum, sumsq
__device__ float g_density[512];
__device__ float g_munorm[128];                // (b,g): mu, rsig
__device__ float g_gates[32];                  // (b, k)

// ---------------- K1: density + zero stats ----------------
__global__ void k_density(const float* __restrict__ x) {
    int bc = blockIdx.x;
    const float* xp = x + (size_t)bc * HWSZ;
    int cnt = 0;
    for (int i = threadIdx.x; i < HWSZ; i += 256) cnt += (xp[i] != 0.0f);
    __shared__ int red[256];
    red[threadIdx.x] = cnt; __syncthreads();
    for (int s = 128; s > 0; s >>= 1) {
        if (threadIdx.x < s) red[threadIdx.x] += red[threadIdx.x + s];
        __syncthreads();
    }
    if (threadIdx.x == 0) g_density[bc] = (float)red[0] / (float)HWSZ;
    if (blockIdx.x == 0 && threadIdx.x < 128) g_stats[threadIdx.x] = 0.f;
}

// ---------------- K2: DWT2 -> g_ff ----------------
__global__ void __launch_bounds__(256) k_dwt(const float* __restrict__ x) {
    const int tile = blockIdx.x;          // 0..24
    const int bc = blockIdx.y;            // 0..511
    const int i0 = (tile / 5) * 32;
    const int j0 = (tile % 5) * 32;
    __shared__ float sIn[70][72];
    __shared__ float sT[2][70][33];
    const float* xp = x + (size_t)bc * HWSZ;

    for (int idx = threadIdx.x; idx < 70 * 70; idx += 256) {
        int r = idx / 70, s = idx % 70;
        int m = 2 * i0 - 6 + r;
        int n = 2 * j0 - 6 + s;
        m = (m < 0) ? (-1 - m) : ((m > 255) ? (511 - m) : m);
        n = (n < 0) ? (-1 - n) : ((n > 255) ? (511 - n) : n);
        sIn[r][s] = xp[m * 256 + n];
    }
    __syncthreads();
    for (int idx = threadIdx.x; idx < 70 * 32; idx += 256) {
        int r = idx / 32, j = idx % 32;
        float lo = 0.f, hi = 0.f;
        #pragma unroll
        for (int v = 0; v < 8; v++) {
            float xv = sIn[r][2 * j + v];
            lo += xv * DEC_LO[7 - v];
            hi += xv * DEC_HI[7 - v];
        }
        sT[0][r][j] = lo; sT[1][r][j] = hi;
    }
    __syncthreads();
    int b = bc >> 6, c = bc & 63;
    float* base = g_ff + ((size_t)b * 256 + c) * PSTR;
    for (int idx = threadIdx.x; idx < 32 * 32; idx += 256) {
        int i = idx / 32, j = idx % 32;
        int gi = i0 + i, gj = j0 + j;
        if (gi < OHH && gj < OWW) {
            float aa = 0.f, da = 0.f, ad = 0.f, dd = 0.f;
            #pragma unroll
            for (int u = 0; u < 8; u++) {
                float tl = sT[0][2 * i + u][j], th = sT[1][2 * i + u][j];
                float gl = DEC_LO[7 - u], gh = DEC_HI[7 - u];
                aa += gl * tl; da += gh * tl; ad += gl * th; dd += gh * th;
            }
            int p = gi * OWW + gj;
            base[p] = aa;
            base[(size_t)64 * PSTR + p] = da;
            base[(size_t)128 * PSTR + p] = ad;
            base[(size_t)192 * PSTR + p] = dd;
        }
    }
}

// ---------------- K3: z = ff @ w1^T + b1, + GN stats ----------------
__global__ void __launch_bounds__(256) k_gemm1(const float* __restrict__ w1,
                                               const float* __restrict__ b1) {
    int b = blockIdx.y;
    int p0 = blockIdx.x * 128;
    __shared__ float sA[16][132];
    __shared__ float sWt[16][132];
    int tx = threadIdx.x & 15, ty = threadIdx.x >> 4;
    float acc[8][8] = {};
    const float* ffb = g_ff + (size_t)b * 256 * PSTR;

    for (int qc = 0; qc < 256; qc += 16) {
        for (int idx = threadIdx.x; idx < 16 * 128; idx += 256) {
            int r = idx >> 7, j = idx & 127;
            int p = p0 + j;
            sA[r][j] = (p < PP) ? ffb[(size_t)(qc + r) * PSTR + p] : 0.f;
        }
        for (int idx = threadIdx.x; idx < 128 * 16; idx += 256) {
            int o = idx >> 4, r = idx & 15;
            sWt[r][o] = w1[o * 256 + qc + r];
        }
        __syncthreads();
        #pragma unroll
        for (int r = 0; r < 16; r++) {
            float4 a0 = *(float4*)&sA[r][tx * 8];
            float4 a1 = *(float4*)&sA[r][tx * 8 + 4];
            float4 w0 = *(float4*)&sWt[r][ty * 8];
            float4 w1v = *(float4*)&sWt[r][ty * 8 + 4];
            float av[8] = {a0.x,a0.y,a0.z,a0.w,a1.x,a1.y,a1.z,a1.w};
            float wv[8] = {w0.x,w0.y,w0.z,w0.w,w1v.x,w1v.y,w1v.z,w1v.w};
            #pragma unroll
            for (int i = 0; i < 8; i++)
                #pragma unroll
                for (int j = 0; j < 8; j++)
                    acc[i][j] += wv[i] * av[j];
        }
        __syncthreads();
    }
    float s1 = 0.f, s2 = 0.f;
    float* zb = g_z + (size_t)b * 128 * PSTR;
    bool full = (p0 + 128 <= PP);
    #pragma unroll
    for (int i = 0; i < 8; i++) {
        int o = ty * 8 + i;
        float bias = b1[o];
        if (full) {
            float4 v0, v1;
            v0.x = acc[i][0]+bias; v0.y = acc[i][1]+bias; v0.z = acc[i][2]+bias; v0.w = acc[i][3]+bias;
            v1.x = acc[i][4]+bias; v1.y = acc[i][5]+bias; v1.z = acc[i][6]+bias; v1.w = acc[i][7]+bias;
            s1 += v0.x+v0.y+v0.z+v0.w + v1.x+v1.y+v1.z+v1.w;
            s2 += v0.x*v0.x+v0.y*v0.y+v0.z*v0.z+v0.w*v0.w + v1.x*v1.x+v1.y*v1.y+v1.z*v1.z+v1.w*v1.w;
            *(float4*)&zb[(size_t)o * PSTR + p0 + tx * 8] = v0;
            *(float4*)&zb[(size_t)o * PSTR + p0 + tx * 8 + 4] = v1;
        } else {
            #pragma unroll
            for (int j = 0; j < 8; j++) {
                int p = p0 + tx * 8 + j;
                if (p < PP) {
                    float zv = acc[i][j] + bias;
                    zb[(size_t)o * PSTR + p] = zv;
                    s1 += zv; s2 += zv * zv;
                }
            }
        }
    }
    #pragma unroll
    for (int off = 16; off > 0; off >>= 1) {
        s1 += __shfl_down_sync(0xffffffffu, s1, off);
        s2 += __shfl_down_sync(0xffffffffu, s2, off);
    }
    int warp = threadIdx.x >> 5;   // == group index (o_base = ty*8, g = ty/2)
    if ((threadIdx.x & 31) == 0) {
        atomicAdd(&g_stats[(b * 8 + warp) * 2], s1);
        atomicAdd(&g_stats[(b * 8 + warp) * 2 + 1], s2);
    }
}

// ---------------- K4: finalize stats + gates ----------------
__global__ void k_small(const float* __restrict__ g1, const float* __restrict__ gb1,
                        const float* __restrict__ g2, const float* __restrict__ gb2) {
    int t = threadIdx.x;
    if (t < 64) {
        float s1 = g_stats[2 * t], s2 = g_stats[2 * t + 1];
        float invN = 1.f / (16.f * (float)PP);
        float mu = s1 * invN;
        float var = s2 * invN - mu * mu;
        g_munorm[2 * t] = mu;
        g_munorm[2 * t + 1] = rsqrtf(var + 1e-5f);
    } else if (t < 72) {
        int b = t - 64;
        float hv[16];
        for (int i = 0; i < 16; i++) {
            float s = gb1[i];
            for (int c = 0; c < 64; c++) s += g_density[b * 64 + c] * g1[i * 64 + c];
            hv[i] = fmaxf(s, 0.f);
        }
        for (int j = 0; j < 4; j++) {
            float s = gb2[j];
            for (int i = 0; i < 16; i++) s += hv[i] * g2[j * 16 + i];
            g_gates[b * 4 + j] = 1.f / (1.f + expf(-s));
        }
    }
}

// ---------------- K5: gated = (gelu(GN(z)) @ w2^T + b2) * gate ----------------
__global__ void __launch_bounds__(256) k_gemm2(const float* __restrict__ w2,
                                               const float* __restrict__ b2,
                                               const float* __restrict__ gamma,
                                               const float* __restrict__ beta) {
    int b = blockIdx.z;
    int ob = blockIdx.y * 128;
    int p0 = blockIdx.x * 128;
    __shared__ float sA[16][132];
    __shared__ float sWt[16][132];
    __shared__ float sScale[128], sShift[128];
    if (threadIdx.x < 128) {
        int q = threadIdx.x, g = q >> 4;
        float mu = g_munorm[(b * 8 + g) * 2];
        float rs = g_munorm[(b * 8 + g) * 2 + 1];
        float sc = rs * gamma[q];
        sScale[q] = sc;
        sShift[q] = beta[q] - mu * sc;
    }
    __syncthreads();
    int tx = threadIdx.x & 15, ty = threadIdx.x >> 4;
    float acc[8][8] = {};
    const float* zb = g_z + (size_t)b * 128 * PSTR;

    for (int qc = 0; qc < 128; qc += 16) {
        for (int idx = threadIdx.x; idx < 16 * 128; idx += 256) {
            int r = idx >> 7, j = idx & 127;
            int p = p0 + j;
            float raw = (p < PP) ? zb[(size_t)(qc + r) * PSTR + p] : 0.f;
            float v = raw * sScale[qc + r] + sShift[qc + r];
            v = 0.5f * v * (1.f + erff(v * 0.70710678118654752f));
            sA[r][j] = v;
        }
        for (int idx = threadIdx.x; idx < 128 * 16; idx += 256) {
            int o = idx >> 4, r = idx & 15;
            sWt[r][o] = w2[(ob + o) * 128 + qc + r];
        }
        __syncthreads();
        #pragma unroll
        for (int r = 0; r < 16; r++) {
            float4 a0 = *(float4*)&sA[r][tx * 8];
            float4 a1 = *(float4*)&sA[r][tx * 8 + 4];
            float4 w0 = *(float4*)&sWt[r][ty * 8];
            float4 w1v = *(float4*)&sWt[r][ty * 8 + 4];
            float av[8] = {a0.x,a0.y,a0.z,a0.w,a1.x,a1.y,a1.z,a1.w};
            float wv[8] = {w0.x,w0.y,w0.z,w0.w,w1v.x,w1v.y,w1v.z,w1v.w};
            #pragma unroll
            for (int i = 0; i < 8; i++)
                #pragma unroll
                for (int j = 0; j < 8; j++)
                    acc[i][j] += wv[i] * av[j];
        }
        __syncthreads();
    }
    float* gbuf = g_ff + (size_t)b * 256 * PSTR;
    bool full = (p0 + 128 <= PP);
    #pragma unroll
    for (int i = 0; i < 8; i++) {
        int o = ob + ty * 8 + i;
        float bias = b2[o];
        float gate = g_gates[b * 4 + (o >> 6)];
        if (full) {
            float4 v0, v1;
            v0.x=(acc[i][0]+bias)*gate; v0.y=(acc[i][1]+bias)*gate; v0.z=(acc[i][2]+bias)*gate; v0.w=(acc[i][3]+bias)*gate;
            v1.x=(acc[i][4]+bias)*gate; v1.y=(acc[i][5]+bias)*gate; v1.z=(acc[i][6]+bias)*gate; v1.w=(acc[i][7]+bias)*gate;
            *(float4*)&gbuf[(size_t)o * PSTR + p0 + tx * 8] = v0;
            *(float4*)&gbuf[(size_t)o * PSTR + p0 + tx * 8 + 4] = v1;
        } else {
            #pragma unroll
            for (int j = 0; j < 8; j++) {
                int p = p0 + tx * 8 + j;
                if (p < PP) gbuf[(size_t)o * PSTR + p] = (acc[i][j] + bias) * gate;
            }
        }
    }
}

// ---------------- K6: IDWT2 -> g_recon ----------------
__global__ void __launch_bounds__(256) k_idwt() {
    int tile = blockIdx.x;         // 0..31 : 8 h-tiles x 4 w-tiles
    int bc = blockIdx.y;
    int h0 = (tile >> 2) * 32;
    int w0 = (tile & 3) * 64;
    int b = bc >> 6, c = bc & 63;
    __shared__ float scoef[4][19][36];
    __shared__ float stmp[4][19][68];
    const float* gb = g_ff + ((size_t)b * 256 + c) * PSTR;
    int ib0 = h0 >> 1, jb0 = w0 >> 1;

    for (int idx = threadIdx.x; idx < 4 * 19 * 35; idx += 256) {
        int k = idx / (19 * 35); int rem = idx % (19 * 35);
        int il = rem / 35, jl = rem % 35;
        scoef[k][il][jl] = gb[(size_t)k * 64 * PSTR + (ib0 + il) * OWW + jb0 + jl];
    }
    __syncthreads();
    // pass1: column (w) synthesis. col filter lo for k<2, hi for k>=2.
    for (int s = threadIdx.x; s < 19 * 16; s += 256) {
        int il = s >> 4, ws = s & 15;
        int wl = ws * 4, jb = wl >> 1;
        #pragma unroll
        for (int k = 0; k < 4; k++) {
            const float* fc = (k < 2) ? DEC_LO : DEC_HI;
            float c0 = scoef[k][il][jb],     c1 = scoef[k][il][jb + 1];
            float c2 = scoef[k][il][jb + 2], c3 = scoef[k][il][jb + 3];
            float c4 = scoef[k][il][jb + 4];
            stmp[k][il][wl + 0] = c0*fc[1] + c1*fc[3] + c2*fc[5] + c3*fc[7];
            stmp[k][il][wl + 1] = c0*fc[0] + c1*fc[2] + c2*fc[4] + c3*fc[6];
            stmp[k][il][wl + 2] = c1*fc[1] + c2*fc[3] + c3*fc[5] + c4*fc[7];
            stmp[k][il][wl + 3] = c1*fc[0] + c2*fc[2] + c3*fc[4] + c4*fc[6];
        }
    }
    __syncthreads();
    // pass2: row (h) synthesis. row filter hi for k in {1,3}.
    float* rb = g_recon + ((size_t)b * 64 + c) * HWSZ;
    for (int s = threadIdx.x; s < 512; s += 256) {
        int wlh = s & 63, hs = s >> 6;
        int hb = hs * 4, ib = hb >> 1;
        float t[4][5];
        #pragma unroll
        for (int k = 0; k < 4; k++)
            #pragma unroll
            for (int m = 0; m < 5; m++)
                t[k][m] = stmp[k][ib + m][wlh];
        #pragma unroll
        for (int dh = 0; dh < 4; dh++) {
            int sh = dh >> 1;
            float acc = 0.f;
            #pragma unroll
            for (int k = 0; k < 4; k++) {
                const float* fr = (k & 1) ? DEC_HI : DEC_LO;
                if (dh & 1)
                    acc += t[k][sh]*fr[0] + t[k][sh+1]*fr[2] + t[k][sh+2]*fr[4] + t[k][sh+3]*fr[6];
                else
                    acc += t[k][sh]*fr[1] + t[k][sh+1]*fr[3] + t[k][sh+2]*fr[5] + t[k][sh+3]*fr[7];
            }
            rb[(h0 + hb + dh) * WW + w0 + wlh] = acc;
        }
    }
}

// ---------------- K7: fused = [x, recon] @ wf^T + bf ----------------
__global__ void __launch_bounds__(256) k_final(const float* __restrict__ x,
                                               const float* __restrict__ wf,
                                               const float* __restrict__ bf,
                                               float* __restrict__ out) {
    int b = blockIdx.y;
    int p0 = blockIdx.x * 256;
    __shared__ float sIn[16][260];
    __shared__ float sWt[16][68];
    int tx = threadIdx.x & 31, ty = threadIdx.x >> 5;
    float acc[8][8] = {};
    const float* xb = x + (size_t)b * 64 * HWSZ;
    const float* rb = g_recon + (size_t)b * 64 * HWSZ;

    for (int cc = 0; cc < 128; cc += 16) {
        for (int idx = threadIdx.x; idx < 16 * 256; idx += 256) {
            int r = idx >> 8, j = idx & 255;
            int ch = cc + r;
            sIn[r][j] = (ch < 64) ? xb[(size_t)ch * HWSZ + p0 + j]
                                  : rb[(size_t)(ch - 64) * HWSZ + p0 + j];
        }
        for (int idx = threadIdx.x; idx < 64 * 16; idx += 256) {
            int o = idx >> 4, r = idx & 15;
            sWt[r][o] = wf[o * 128 + cc + r];
        }
        __syncthreads();
        #pragma unroll
        for (int r = 0; r < 16; r++) {
            float4 a0 = *(float4*)&sIn[r][tx * 8];
            float4 a1 = *(float4*)&sIn[r][tx * 8 + 4];
            float4 w0 = *(float4*)&sWt[r][ty * 8];
            float4 w1v = *(float4*)&sWt[r][ty * 8 + 4];
            float av[8] = {a0.x,a0.y,a0.z,a0.w,a1.x,a1.y,a1.z,a1.w};
            float wv[8] = {w0.x,w0.y,w0.z,w0.w,w1v.x,w1v.y,w1v.z,w1v.w};
            #pragma unroll
            for (int i = 0; i < 8; i++)
                #pragma unroll
                for (int j = 0; j < 8; j++)
                    acc[i][j] += wv[i] * av[j];
        }
        __syncthreads();
    }
    float* ob = out + (size_t)b * 64 * HWSZ;
    #pragma unroll
    for (int i = 0; i < 8; i++) {
        int o = ty * 8 + i;
        float bias = bf[o];
        float4 v0, v1;
        v0.x = acc[i][0]+bias; v0.y = acc[i][1]+bias; v0.z = acc[i][2]+bias; v0.w = acc[i][3]+bias;
        v1.x = acc[i][4]+bias; v1.y = acc[i][5]+bias; v1.z = acc[i][6]+bias; v1.w = acc[i][7]+bias;
        *(float4*)&ob[(size_t)o * HWSZ + p0 + tx * 8] = v0;
        *(float4*)&ob[(size_t)o * HWSZ + p0 + tx * 8 + 4] = v1;
    }
}

extern "C" void kernel_launch(void* const* d_in, const int* in_sizes, int n_in,
                              void* d_out, int out_size) {
    const float* x     = (const float*)d_in[0];
    const float* w1    = (const float*)d_in[1];
    const float* b1    = (const float*)d_in[2];
    const float* gamma = (const float*)d_in[3];
    const float* beta  = (const float*)d_in[4];
    const float* w2    = (const float*)d_in[5];
    const float* b2    = (const float*)d_in[6];
    const float* g1    = (const float*)d_in[7];
    const float* gb1   = (const float*)d_in[8];
    const float* g2    = (const float*)d_in[9];
    const float* gb2   = (const float*)d_in[10];
    const float* wf    = (const float*)d_in[11];
    const float* bf    = (const float*)d_in[12];
    float* out = (float*)d_out;

    k_density<<<512, 256>>>(x);
    k_dwt<<<dim3(25, 512), 256>>>(x);
    k_gemm1<<<dim3(135, 8), 256>>>(w1, b1);
    k_small<<<1, 128>>>(g1, gb1, g2, gb2);
    k_gemm2<<<dim3(135, 2, 8), 256>>>(w2, b2, gamma, beta);
    k_idwt<<<dim3(32, 512), 256>>>();
    k_final<<<dim3(256, 8), 256>>>(x, wf, bf, out);
}

// round 3
// speedup vs baseline: 1.2181x; 1.2181x over previous
#include <cuda_runtime.h>
#include <stdint.h>
#include <math.h>

#define BB 8
#define CC 64
#define HH 256
#define WW 256
#define OHH 131
#define OWW 131
#define PP (OHH*OWW)      /* 17161 */
#define PSTR 17164        /* padded channel stride (multiple of 4) */
#define HWSZ (HH*WW)      /* 65536 */

// db4 filters
__constant__ float DEC_LO[8] = {
    -0.010597401784997278f, 0.032883011666982945f, 0.030841381835986965f,
    -0.18703481171888114f, -0.02798376941698385f, 0.6308807679295904f,
    0.7148465705525415f, 0.23037781330885523f };
__constant__ float DEC_HI[8] = {
    -0.23037781330885523f, 0.7148465705525415f, -0.6308807679295904f,
    -0.02798376941698385f, 0.18703481171888114f, 0.030841381835986965f,
    -0.032883011666982945f, -0.010597401784997278f };

// Scratch (device globals; allocation-free rule)
__device__ float g_ff[(size_t)BB*256*PSTR];    // ff then gated coeffs, (b, q=k*64+c, p)
__device__ float g_z[(size_t)BB*128*PSTR];     // z pre-GN, (b, o, p)
__device__ float g_recon[(size_t)BB*64*HWSZ];  // (b, c, h, w)
__device__ float g_stats[128];                 // (b,g): sum, sumsq
__device__ float g_density[512];
__device__ float g_munorm[128];                // (b,g): mu, rsig
__device__ float g_gates[32];                  // (b, k)

// ---- tf32 helpers ----
__device__ __forceinline__ uint32_t f2tf32(float x) {
    uint32_t r; asm("cvt.rna.tf32.f32 %0, %1;" : "=r"(r) : "f"(x)); return r;
}
__device__ __forceinline__ void mma_tf32(float4& d, const uint32_t a[4], const uint32_t b[2]) {
    asm volatile("mma.sync.aligned.m16n8k8.row.col.f32.tf32.tf32.f32 "
        "{%0,%1,%2,%3}, {%4,%5,%6,%7}, {%8,%9}, {%0,%1,%2,%3};"
        : "+f"(d.x), "+f"(d.y), "+f"(d.z), "+f"(d.w)
        : "r"(a[0]), "r"(a[1]), "r"(a[2]), "r"(a[3]), "r"(b[0]), "r"(b[1]));
}

// ---------------- K1: density + zero stats ----------------
__global__ void k_density(const float* __restrict__ x) {
    int bc = blockIdx.x;
    const float4* xp = (const float4*)(x + (size_t)bc * HWSZ);
    int cnt = 0;
    for (int i = threadIdx.x; i < HWSZ/4; i += 256) {
        float4 v = xp[i];
        cnt += (v.x != 0.f) + (v.y != 0.f) + (v.z != 0.f) + (v.w != 0.f);
    }
    __shared__ int red[256];
    red[threadIdx.x] = cnt; __syncthreads();
    for (int s = 128; s > 0; s >>= 1) {
        if (threadIdx.x < s) red[threadIdx.x] += red[threadIdx.x + s];
        __syncthreads();
    }
    if (threadIdx.x == 0) g_density[bc] = (float)red[0] / (float)HWSZ;
    if (blockIdx.x == 0 && threadIdx.x < 128) g_stats[threadIdx.x] = 0.f;
}

// ---------------- K2: DWT2 -> g_ff ----------------
__global__ void __launch_bounds__(256) k_dwt(const float* __restrict__ x) {
    const int tile = blockIdx.x;          // 0..24
    const int bc = blockIdx.y;            // 0..511
    const int i0 = (tile / 5) * 32;
    const int j0 = (tile % 5) * 32;
    __shared__ float sIn[70][72];
    __shared__ float sT[2][70][33];
    const float* xp = x + (size_t)bc * HWSZ;

    for (int idx = threadIdx.x; idx < 70 * 70; idx += 256) {
        int r = idx / 70, s = idx % 70;
        int m = 2 * i0 - 6 + r;
        int n = 2 * j0 - 6 + s;
        m = (m < 0) ? (-1 - m) : ((m > 255) ? (511 - m) : m);
        n = (n < 0) ? (-1 - n) : ((n > 255) ? (511 - n) : n);
        sIn[r][s] = xp[m * 256 + n];
    }
    __syncthreads();
    for (int idx = threadIdx.x; idx < 70 * 32; idx += 256) {
        int r = idx / 32, j = idx % 32;
        float lo = 0.f, hi = 0.f;
        #pragma unroll
        for (int v = 0; v < 8; v++) {
            float xv = sIn[r][2 * j + v];
            lo += xv * DEC_LO[7 - v];
            hi += xv * DEC_HI[7 - v];
        }
        sT[0][r][j] = lo; sT[1][r][j] = hi;
    }
    __syncthreads();
    int b = bc >> 6, c = bc & 63;
    float* base = g_ff + ((size_t)b * 256 + c) * PSTR;
    for (int idx = threadIdx.x; idx < 32 * 32; idx += 256) {
        int i = idx / 32, j = idx % 32;
        int gi = i0 + i, gj = j0 + j;
        if (gi < OHH && gj < OWW) {
            float aa = 0.f, da = 0.f, ad = 0.f, dd = 0.f;
            #pragma unroll
            for (int u = 0; u < 8; u++) {
                float tl = sT[0][2 * i + u][j], th = sT[1][2 * i + u][j];
                float gl = DEC_LO[7 - u], gh = DEC_HI[7 - u];
                aa += gl * tl; da += gh * tl; ad += gl * th; dd += gh * th;
            }
            int p = gi * OWW + gj;
            base[p] = aa;
            base[(size_t)64 * PSTR + p] = da;
            base[(size_t)128 * PSTR + p] = ad;
            base[(size_t)192 * PSTR + p] = dd;
        }
    }
}

// ---------------- K3: z = ff @ w1^T + b1, + GN stats (tf32 tensor) ----------------
__global__ void __launch_bounds__(256) k_gemm1(const float* __restrict__ w1,
                                               const float* __restrict__ b1) {
    int b = blockIdx.y;
    int p0 = blockIdx.x * 128;
    __shared__ uint32_t sW[128][20];
    __shared__ uint32_t sA[16][132];
    const int tid = threadIdx.x;
    const int w = tid >> 5, lane = tid & 31;
    const int gid = lane >> 2, tig = lane & 3;
    const int obase = (w >> 1) * 32, pbase = (w & 1) * 64;
    float4 acc[2][8] = {};
    const float* ffb = g_ff + (size_t)b * 256 * PSTR;

    for (int qc = 0; qc < 256; qc += 16) {
        for (int i = tid; i < 2048; i += 256) {
            int r = i >> 7, j = i & 127;
            int p = p0 + j;
            float v = (p < PP) ? ffb[(size_t)(qc + r) * PSTR + p] : 0.f;
            sA[r][j] = f2tf32(v);
        }
        for (int i = tid; i < 2048; i += 256) {
            int o = i >> 4, r = i & 15;
            sW[o][r] = f2tf32(w1[o * 256 + qc + r]);
        }
        __syncthreads();
        #pragma unroll
        for (int ks = 0; ks < 2; ks++) {
            int k0 = ks * 8;
            uint32_t afr[2][4];
            #pragma unroll
            for (int mt = 0; mt < 2; mt++) {
                int o = obase + mt * 16 + gid;
                afr[mt][0] = sW[o][k0 + tig];
                afr[mt][1] = sW[o + 8][k0 + tig];
                afr[mt][2] = sW[o][k0 + tig + 4];
                afr[mt][3] = sW[o + 8][k0 + tig + 4];
            }
            #pragma unroll
            for (int nt = 0; nt < 8; nt++) {
                uint32_t bfr[2];
                int p = pbase + nt * 8 + gid;
                bfr[0] = sA[k0 + tig][p];
                bfr[1] = sA[k0 + tig + 4][p];
                mma_tf32(acc[0][nt], afr[0], bfr);
                mma_tf32(acc[1][nt], afr[1], bfr);
            }
        }
        __syncthreads();
    }
    // epilogue: +bias, store z, GN stats (group = w>>1*2 + mt)
    float s1[2] = {0.f, 0.f}, s2[2] = {0.f, 0.f};
    float* zb = g_z + (size_t)b * 128 * PSTR;
    bool full = (p0 + 128 <= PP);
    #pragma unroll
    for (int mt = 0; mt < 2; mt++) {
        int o1 = obase + mt * 16 + gid;
        float bia = b1[o1], bib = b1[o1 + 8];
        #pragma unroll
        for (int nt = 0; nt < 8; nt++) {
            int p = p0 + pbase + nt * 8 + 2 * tig;
            float vx = acc[mt][nt].x + bia, vy = acc[mt][nt].y + bia;
            float vz = acc[mt][nt].z + bib, vw = acc[mt][nt].w + bib;
            if (full) {
                s1[mt] += vx + vy + vz + vw;
                s2[mt] += vx*vx + vy*vy + vz*vz + vw*vw;
                *(float2*)&zb[(size_t)o1 * PSTR + p] = make_float2(vx, vy);
                *(float2*)&zb[(size_t)(o1 + 8) * PSTR + p] = make_float2(vz, vw);
            } else {
                if (p < PP)     { zb[(size_t)o1*PSTR + p] = vx;       zb[(size_t)(o1+8)*PSTR + p] = vz;       s1[mt] += vx + vz; s2[mt] += vx*vx + vz*vz; }
                if (p + 1 < PP) { zb[(size_t)o1*PSTR + p + 1] = vy;   zb[(size_t)(o1+8)*PSTR + p + 1] = vw;   s1[mt] += vy + vw; s2[mt] += vy*vy + vw*vw; }
            }
        }
    }
    #pragma unroll
    for (int off = 16; off > 0; off >>= 1) {
        s1[0] += __shfl_down_sync(0xffffffffu, s1[0], off);
        s2[0] += __shfl_down_sync(0xffffffffu, s2[0], off);
        s1[1] += __shfl_down_sync(0xffffffffu, s1[1], off);
        s2[1] += __shfl_down_sync(0xffffffffu, s2[1], off);
    }
    if (lane == 0) {
        int g0 = (w >> 1) * 2;
        atomicAdd(&g_stats[(b * 8 + g0) * 2],     s1[0]);
        atomicAdd(&g_stats[(b * 8 + g0) * 2 + 1], s2[0]);
        atomicAdd(&g_stats[(b * 8 + g0 + 1) * 2],     s1[1]);
        atomicAdd(&g_stats[(b * 8 + g0 + 1) * 2 + 1], s2[1]);
    }
}

// ---------------- K4: finalize stats + gates ----------------
__global__ void k_small(const float* __restrict__ g1, const float* __restrict__ gb1,
                        const float* __restrict__ g2, const float* __restrict__ gb2) {
    int t = threadIdx.x;
    if (t < 64) {
        float s1 = g_stats[2 * t], s2 = g_stats[2 * t + 1];
        float invN = 1.f / (16.f * (float)PP);
        float mu = s1 * invN;
        float var = s2 * invN - mu * mu;
        g_munorm[2 * t] = mu;
        g_munorm[2 * t + 1] = rsqrtf(var + 1e-5f);
    } else if (t < 72) {
        int b = t - 64;
        float hv[16];
        for (int i = 0; i < 16; i++) {
            float s = gb1[i];
            for (int c = 0; c < 64; c++) s += g_density[b * 64 + c] * g1[i * 64 + c];
            hv[i] = fmaxf(s, 0.f);
        }
        for (int j = 0; j < 4; j++) {
            float s = gb2[j];
            for (int i = 0; i < 16; i++) s += hv[i] * g2[j * 16 + i];
            g_gates[b * 4 + j] = 1.f / (1.f + expf(-s));
        }
    }
}

// ---------------- K5: gated = (gelu(GN(z)) @ w2^T + b2) * gate (tf32 tensor) ----------------
__global__ void __launch_bounds__(256) k_gemm2(const float* __restrict__ w2,
                                               const float* __restrict__ b2,
                                               const float* __restrict__ gamma,
                                               const float* __restrict__ beta) {
    int b = blockIdx.z;
    int ob = blockIdx.y * 128;
    int p0 = blockIdx.x * 128;
    __shared__ uint32_t sW[128][20];
    __shared__ uint32_t sA[16][132];
    __shared__ float sScale[128], sShift[128];
    const int tid = threadIdx.x;
    if (tid < 128) {
        int q = tid, g = q >> 4;
        float mu = g_munorm[(b * 8 + g) * 2];
        float rs = g_munorm[(b * 8 + g) * 2 + 1];
        float sc = rs * gamma[q];
        sScale[q] = sc;
        sShift[q] = beta[q] - mu * sc;
    }
    __syncthreads();
    const int w = tid >> 5, lane = tid & 31;
    const int gid = lane >> 2, tig = lane & 3;
    const int obase = (w >> 1) * 32, pbase = (w & 1) * 64;
    float4 acc[2][8] = {};
    const float* zb = g_z + (size_t)b * 128 * PSTR;

    for (int qc = 0; qc < 128; qc += 16) {
        for (int i = tid; i < 2048; i += 256) {
            int r = i >> 7, j = i & 127;
            int p = p0 + j;
            float raw = (p < PP) ? zb[(size_t)(qc + r) * PSTR + p] : 0.f;
            float v = raw * sScale[qc + r] + sShift[qc + r];
            v = 0.5f * v * (1.f + erff(v * 0.70710678118654752f));
            sA[r][j] = f2tf32(v);
        }
        for (int i = tid; i < 2048; i += 256) {
            int o = i >> 4, r = i & 15;
            sW[o][r] = f2tf32(w2[(ob + o) * 128 + qc + r]);
        }
        __syncthreads();
        #pragma unroll
        for (int ks = 0; ks < 2; ks++) {
            int k0 = ks * 8;
            uint32_t afr[2][4];
            #pragma unroll
            for (int mt = 0; mt < 2; mt++) {
                int o = obase + mt * 16 + gid;
                afr[mt][0] = sW[o][k0 + tig];
                afr[mt][1] = sW[o + 8][k0 + tig];
                afr[mt][2] = sW[o][k0 + tig + 4];
                afr[mt][3] = sW[o + 8][k0 + tig + 4];
            }
            #pragma unroll
            for (int nt = 0; nt < 8; nt++) {
                uint32_t bfr[2];
                int p = pbase + nt * 8 + gid;
                bfr[0] = sA[k0 + tig][p];
                bfr[1] = sA[k0 + tig + 4][p];
                mma_tf32(acc[0][nt], afr[0], bfr);
                mma_tf32(acc[1][nt], afr[1], bfr);
            }
        }
        __syncthreads();
    }
    float* gbuf = g_ff + (size_t)b * 256 * PSTR;
    bool full = (p0 + 128 <= PP);
    #pragma unroll
    for (int mt = 0; mt < 2; mt++) {
        int o1 = ob + obase + mt * 16 + gid;
        float ga = g_gates[b * 4 + (o1 >> 6)];
        float gb_ = g_gates[b * 4 + ((o1 + 8) >> 6)];
        float bia = b2[o1], bib = b2[o1 + 8];
        #pragma unroll
        for (int nt = 0; nt < 8; nt++) {
            int p = p0 + pbase + nt * 8 + 2 * tig;
            float vx = (acc[mt][nt].x + bia) * ga, vy = (acc[mt][nt].y + bia) * ga;
            float vz = (acc[mt][nt].z + bib) * gb_, vw = (acc[mt][nt].w + bib) * gb_;
            if (full) {
                *(float2*)&gbuf[(size_t)o1 * PSTR + p] = make_float2(vx, vy);
                *(float2*)&gbuf[(size_t)(o1 + 8) * PSTR + p] = make_float2(vz, vw);
            } else {
                if (p < PP)     { gbuf[(size_t)o1*PSTR + p] = vx;     gbuf[(size_t)(o1+8)*PSTR + p] = vz; }
                if (p + 1 < PP) { gbuf[(size_t)o1*PSTR + p + 1] = vy; gbuf[(size_t)(o1+8)*PSTR + p + 1] = vw; }
            }
        }
    }
}

// ---------------- K6: IDWT2 -> g_recon ----------------
__global__ void __launch_bounds__(256) k_idwt() {
    int tile = blockIdx.x;         // 0..31 : 8 h-tiles x 4 w-tiles
    int bc = blockIdx.y;
    int h0 = (tile >> 2) * 32;
    int w0 = (tile & 3) * 64;
    int b = bc >> 6, c = bc & 63;
    __shared__ float scoef[4][19][36];
    __shared__ float stmp[4][19][68];
    const float* gb = g_ff + ((size_t)b * 256 + c) * PSTR;
    int ib0 = h0 >> 1, jb0 = w0 >> 1;

    for (int idx = threadIdx.x; idx < 4 * 19 * 35; idx += 256) {
        int k = idx / (19 * 35); int rem = idx % (19 * 35);
        int il = rem / 35, jl = rem % 35;
        scoef[k][il][jl] = gb[(size_t)k * 64 * PSTR + (ib0 + il) * OWW + jb0 + jl];
    }
    __syncthreads();
    for (int s = threadIdx.x; s < 19 * 16; s += 256) {
        int il = s >> 4, ws = s & 15;
        int wl = ws * 4, jb = wl >> 1;
        #pragma unroll
        for (int k = 0; k < 4; k++) {
            const float* fc = (k < 2) ? DEC_LO : DEC_HI;
            float c0 = scoef[k][il][jb],     c1 = scoef[k][il][jb + 1];
            float c2 = scoef[k][il][jb + 2], c3 = scoef[k][il][jb + 3];
            float c4 = scoef[k][il][jb + 4];
            stmp[k][il][wl + 0] = c0*fc[1] + c1*fc[3] + c2*fc[5] + c3*fc[7];
            stmp[k][il][wl + 1] = c0*fc[0] + c1*fc[2] + c2*fc[4] + c3*fc[6];
            stmp[k][il][wl + 2] = c1*fc[1] + c2*fc[3] + c3*fc[5] + c4*fc[7];
            stmp[k][il][wl + 3] = c1*fc[0] + c2*fc[2] + c3*fc[4] + c4*fc[6];
        }
    }
    __syncthreads();
    float* rb = g_recon + ((size_t)b * 64 + c) * HWSZ;
    for (int s = threadIdx.x; s < 512; s += 256) {
        int wlh = s & 63, hs = s >> 6;
        int hb = hs * 4, ib = hb >> 1;
        float t[4][5];
        #pragma unroll
        for (int k = 0; k < 4; k++)
            #pragma unroll
            for (int m = 0; m < 5; m++)
                t[k][m] = stmp[k][ib + m][wlh];
        #pragma unroll
        for (int dh = 0; dh < 4; dh++) {
            int sh = dh >> 1;
            float acc = 0.f;
            #pragma unroll
            for (int k = 0; k < 4; k++) {
                const float* fr = (k & 1) ? DEC_HI : DEC_LO;
                if (dh & 1)
                    acc += t[k][sh]*fr[0] + t[k][sh+1]*fr[2] + t[k][sh+2]*fr[4] + t[k][sh+3]*fr[6];
                else
                    acc += t[k][sh]*fr[1] + t[k][sh+1]*fr[3] + t[k][sh+2]*fr[5] + t[k][sh+3]*fr[7];
            }
            rb[(h0 + hb + dh) * WW + w0 + wlh] = acc;
        }
    }
}

// ---------------- K7: fused = [x, recon] @ wf^T + bf (tf32 tensor) ----------------
__global__ void __launch_bounds__(256) k_final(const float* __restrict__ x,
                                               const float* __restrict__ wf,
                                               const float* __restrict__ bf,
                                               float* __restrict__ out) {
    int b = blockIdx.y;
    int p0 = blockIdx.x * 256;
    __shared__ uint32_t sW[64][20];
    __shared__ uint32_t sA[16][260];
    const int tid = threadIdx.x;
    const int w = tid >> 5, lane = tid & 31;
    const int gid = lane >> 2, tig = lane & 3;
    const int obase = (w >> 2) * 32, pbase = (w & 3) * 64;
    float4 acc[2][8] = {};
    const float* xb = x + (size_t)b * 64 * HWSZ;
    const float* rb = g_recon + (size_t)b * 64 * HWSZ;

    for (int cc = 0; cc < 128; cc += 16) {
        for (int i = tid; i < 4096; i += 256) {
            int r = i >> 8, j = i & 255;
            int ch = cc + r;
            float v = (ch < 64) ? xb[(size_t)ch * HWSZ + p0 + j]
                                : rb[(size_t)(ch - 64) * HWSZ + p0 + j];
            sA[r][j] = f2tf32(v);
        }
        for (int i = tid; i < 1024; i += 256) {
            int o = i >> 4, r = i & 15;
            sW[o][r] = f2tf32(wf[o * 128 + cc + r]);
        }
        __syncthreads();
        #pragma unroll
        for (int ks = 0; ks < 2; ks++) {
            int k0 = ks * 8;
            uint32_t afr[2][4];
            #pragma unroll
            for (int mt = 0; mt < 2; mt++) {
                int o = obase + mt * 16 + gid;
                afr[mt][0] = sW[o][k0 + tig];
                afr[mt][1] = sW[o + 8][k0 + tig];
                afr[mt][2] = sW[o][k0 + tig + 4];
                afr[mt][3] = sW[o + 8][k0 + tig + 4];
            }
            #pragma unroll
            for (int nt = 0; nt < 8; nt++) {
                uint32_t bfr[2];
                int p = pbase + nt * 8 + gid;
                bfr[0] = sA[k0 + tig][p];
                bfr[1] = sA[k0 + tig + 4][p];
                mma_tf32(acc[0][nt], afr[0], bfr);
                mma_tf32(acc[1][nt], afr[1], bfr);
            }
        }
        __syncthreads();
    }
    float* ob = out + (size_t)b * 64 * HWSZ;
    #pragma unroll
    for (int mt = 0; mt < 2; mt++) {
        int o1 = obase + mt * 16 + gid;
        float bia = bf[o1], bib = bf[o1 + 8];
        #pragma unroll
        for (int nt = 0; nt < 8; nt++) {
            int p = p0 + pbase + nt * 8 + 2 * tig;
            *(float2*)&ob[(size_t)o1 * HWSZ + p] = make_float2(acc[mt][nt].x + bia, acc[mt][nt].y + bia);
            *(float2*)&ob[(size_t)(o1 + 8) * HWSZ + p] = make_float2(acc[mt][nt].z + bib, acc[mt][nt].w + bib);
        }
    }
}

extern "C" void kernel_launch(void* const* d_in, const int* in_sizes, int n_in,
                              void* d_out, int out_size) {
    const float* x     = (const float*)d_in[0];
    const float* w1    = (const float*)d_in[1];
    const float* b1    = (const float*)d_in[2];
    const float* gamma = (const float*)d_in[3];
    const float* beta  = (const float*)d_in[4];
    const float* w2    = (const float*)d_in[5];
    const float* b2    = (const float*)d_in[6];
    const float* g1    = (const float*)d_in[7];
    const float* gb1   = (const float*)d_in[8];
    const float* g2    = (const float*)d_in[9];
    const float* gb2   = (const float*)d_in[10];
    const float* wf    = (const float*)d_in[11];
    const float* bf    = (const float*)d_in[12];
    float* out = (float*)d_out;

    k_density<<<512, 256>>>(x);
    k_dwt<<<dim3(25, 512), 256>>>(x);
    k_gemm1<<<dim3(135, 8), 256>>>(w1, b1);
    k_small<<<1, 128>>>(g1, gb1, g2, gb2);
    k_gemm2<<<dim3(135, 2, 8), 256>>>(w2, b2, gamma, beta);
    k_idwt<<<dim3(32, 512), 256>>>();
    k_final<<<dim3(256, 8), 256>>>(x, wf, bf, out);
}

// round 4
// speedup vs baseline: 2.1576x; 1.7713x over previous
#include <cuda_runtime.h>
#include <stdint.h>
#include <math.h>

#define BB 8
#define CC 64
#define HH 256
#define WW 256
#define OHH 131
#define OWW 131
#define PP (OHH*OWW)      /* 17161 */
#define PSTR 17164        /* padded channel stride (multiple of 4) */
#define HWSZ (HH*WW)      /* 65536 */

// db4 filters
__constant__ float DEC_LO[8] = {
    -0.010597401784997278f, 0.032883011666982945f, 0.030841381835986965f,
    -0.18703481171888114f, -0.02798376941698385f, 0.6308807679295904f,
    0.7148465705525415f, 0.23037781330885523f };
__constant__ float DEC_HI[8] = {
    -0.23037781330885523f, 0.7148465705525415f, -0.6308807679295904f,
    -0.02798376941698385f, 0.18703481171888114f, 0.030841381835986965f,
    -0.032883011666982945f, -0.010597401784997278f };

// Scratch (device globals; allocation-free rule)
__device__ float g_ff[(size_t)BB*256*PSTR];    // ff then gated coeffs, (b, q=k*64+c, p)
__device__ float g_z[(size_t)BB*128*PSTR];     // z pre-GN, (b, o, p)
__device__ float g_recon[(size_t)BB*64*HWSZ];  // (b, c, h, w)
__device__ float g_stats[128];                 // (b,g): sum, sumsq
__device__ float g_density[512];
__device__ float g_munorm[128];                // (b,g): mu, rsig
__device__ float g_gates[32];                  // (b, k)

// ---- tf32 helpers ----
__device__ __forceinline__ uint32_t f2tf32(float x) {
    uint32_t r; asm("cvt.rna.tf32.f32 %0, %1;" : "=r"(r) : "f"(x)); return r;
}
__device__ __forceinline__ void mma_tf32(float4& d, const uint32_t a[4], const uint32_t b[2]) {
    asm volatile("mma.sync.aligned.m16n8k8.row.col.f32.tf32.tf32.f32 "
        "{%0,%1,%2,%3}, {%4,%5,%6,%7}, {%8,%9}, {%0,%1,%2,%3};"
        : "+f"(d.x), "+f"(d.y), "+f"(d.z), "+f"(d.w)
        : "r"(a[0]), "r"(a[1]), "r"(a[2]), "r"(a[3]), "r"(b[0]), "r"(b[1]));
}
__device__ __forceinline__ uint4 tf4(float4 v) {
    uint4 u; u.x = f2tf32(v.x); u.y = f2tf32(v.y); u.z = f2tf32(v.z); u.w = f2tf32(v.w);
    return u;
}

// ---------------- K1: density + zero stats ----------------
__global__ void k_density(const float* __restrict__ x) {
    int bc = blockIdx.x;
    const float4* xp = (const float4*)(x + (size_t)bc * HWSZ);
    int cnt = 0;
    for (int i = threadIdx.x; i < HWSZ/4; i += 256) {
        float4 v = xp[i];
        cnt += (v.x != 0.f) + (v.y != 0.f) + (v.z != 0.f) + (v.w != 0.f);
    }
    __shared__ int red[256];
    red[threadIdx.x] = cnt; __syncthreads();
    for (int s = 128; s > 0; s >>= 1) {
        if (threadIdx.x < s) red[threadIdx.x] += red[threadIdx.x + s];
        __syncthreads();
    }
    if (threadIdx.x == 0) g_density[bc] = (float)red[0] / (float)HWSZ;
    if (blockIdx.x == 0 && threadIdx.x < 128) g_stats[threadIdx.x] = 0.f;
}

// ---------------- K2: DWT2 -> g_ff ----------------
__global__ void __launch_bounds__(256) k_dwt(const float* __restrict__ x) {
    const int tile = blockIdx.x;          // 0..24
    const int bc = blockIdx.y;            // 0..511
    const int i0 = (tile / 5) * 32;
    const int j0 = (tile % 5) * 32;
    __shared__ float sIn[70][72];
    __shared__ float sT[2][70][33];
    const float* xp = x + (size_t)bc * HWSZ;

    for (int idx = threadIdx.x; idx < 70 * 70; idx += 256) {
        int r = idx / 70, s = idx % 70;
        int m = 2 * i0 - 6 + r;
        int n = 2 * j0 - 6 + s;
        m = (m < 0) ? (-1 - m) : ((m > 255) ? (511 - m) : m);
        n = (n < 0) ? (-1 - n) : ((n > 255) ? (511 - n) : n);
        sIn[r][s] = xp[m * 256 + n];
    }
    __syncthreads();
    for (int idx = threadIdx.x; idx < 70 * 32; idx += 256) {
        int r = idx / 32, j = idx % 32;
        float lo = 0.f, hi = 0.f;
        #pragma unroll
        for (int v = 0; v < 8; v++) {
            float xv = sIn[r][2 * j + v];
            lo += xv * DEC_LO[7 - v];
            hi += xv * DEC_HI[7 - v];
        }
        sT[0][r][j] = lo; sT[1][r][j] = hi;
    }
    __syncthreads();
    int b = bc >> 6, c = bc & 63;
    float* base = g_ff + ((size_t)b * 256 + c) * PSTR;
    for (int idx = threadIdx.x; idx < 32 * 32; idx += 256) {
        int i = idx / 32, j = idx % 32;
        int gi = i0 + i, gj = j0 + j;
        if (gi < OHH && gj < OWW) {
            float aa = 0.f, da = 0.f, ad = 0.f, dd = 0.f;
            #pragma unroll
            for (int u = 0; u < 8; u++) {
                float tl = sT[0][2 * i + u][j], th = sT[1][2 * i + u][j];
                float gl = DEC_LO[7 - u], gh = DEC_HI[7 - u];
                aa += gl * tl; da += gh * tl; ad += gl * th; dd += gh * th;
            }
            int p = gi * OWW + gj;
            base[p] = aa;
            base[(size_t)64 * PSTR + p] = da;
            base[(size_t)128 * PSTR + p] = ad;
            base[(size_t)192 * PSTR + p] = dd;
        }
    }
}

// ---------------- K3: z = ff @ w1^T + b1, + GN stats (tf32 tensor, pipelined) ----------------
__global__ void __launch_bounds__(256) k_gemm1(const float* __restrict__ w1,
                                               const float* __restrict__ b1) {
    const int b = blockIdx.y;
    const int p0 = blockIdx.x * 128;
    __shared__ uint32_t sW[2][128][20];
    __shared__ uint32_t sA[2][16][136];
    const int tid = threadIdx.x;
    const int w = tid >> 5, lane = tid & 31;
    const int gid = lane >> 2, tig = lane & 3;
    const int obase = (w >> 1) * 32, pbase = (w & 1) * 64;
    float4 acc[2][8] = {};
    const float* ffb = g_ff + (size_t)b * 256 * PSTR;
    const bool fullA = (p0 + 128 <= PP);

    // per-thread tile coordinates
    const int ar0 = tid >> 5, ac0 = (tid & 31) * 4;           // A: rows 0-7 (s0), 8-15 (s1)
    const int wo0 = tid >> 2, wq0 = (tid & 3) * 4;            // W: o 0-63 (s0), 64-127 (s1)
    float4 ra0, ra1, rw0, rw1;

    // ---- LOAD(qc) macro ----
    #define G1_LOAD(qc) do { \
        if (fullA) { \
            ra0 = *(const float4*)&ffb[(size_t)((qc) + ar0) * PSTR + p0 + ac0]; \
            ra1 = *(const float4*)&ffb[(size_t)((qc) + ar0 + 8) * PSTR + p0 + ac0]; \
        } else { \
            const float* r0p = &ffb[(size_t)((qc) + ar0) * PSTR]; \
            const float* r1p = &ffb[(size_t)((qc) + ar0 + 8) * PSTR]; \
            ra0.x = (p0+ac0   < PP) ? r0p[p0+ac0]   : 0.f; \
            ra0.y = (p0+ac0+1 < PP) ? r0p[p0+ac0+1] : 0.f; \
            ra0.z = (p0+ac0+2 < PP) ? r0p[p0+ac0+2] : 0.f; \
            ra0.w = (p0+ac0+3 < PP) ? r0p[p0+ac0+3] : 0.f; \
            ra1.x = (p0+ac0   < PP) ? r1p[p0+ac0]   : 0.f; \
            ra1.y = (p0+ac0+1 < PP) ? r1p[p0+ac0+1] : 0.f; \
            ra1.z = (p0+ac0+2 < PP) ? r1p[p0+ac0+2] : 0.f; \
            ra1.w = (p0+ac0+3 < PP) ? r1p[p0+ac0+3] : 0.f; \
        } \
        rw0 = *(const float4*)&w1[wo0 * 256 + (qc) + wq0]; \
        rw1 = *(const float4*)&w1[(wo0 + 64) * 256 + (qc) + wq0]; \
    } while (0)
    #define G1_STORE(st) do { \
        *(uint4*)&sA[st][ar0][ac0]     = tf4(ra0); \
        *(uint4*)&sA[st][ar0 + 8][ac0] = tf4(ra1); \
        *(uint4*)&sW[st][wo0][wq0]       = tf4(rw0); \
        *(uint4*)&sW[st][wo0 + 64][wq0]  = tf4(rw1); \
    } while (0)

    G1_LOAD(0); G1_STORE(0);
    __syncthreads();
    int cur = 0;
    for (int qc = 0; qc < 256; qc += 16) {
        const bool hasnext = (qc + 16 < 256);
        if (hasnext) G1_LOAD(qc + 16);
        #pragma unroll
        for (int ks = 0; ks < 2; ks++) {
            int k0 = ks * 8;
            uint32_t afr[2][4];
            #pragma unroll
            for (int mt = 0; mt < 2; mt++) {
                int o = obase + mt * 16 + gid;
                afr[mt][0] = sW[cur][o][k0 + tig];
                afr[mt][1] = sW[cur][o + 8][k0 + tig];
                afr[mt][2] = sW[cur][o][k0 + tig + 4];
                afr[mt][3] = sW[cur][o + 8][k0 + tig + 4];
            }
            #pragma unroll
            for (int nt = 0; nt < 8; nt++) {
                uint32_t bfr[2];
                int p = pbase + nt * 8 + gid;
                bfr[0] = sA[cur][k0 + tig][p];
                bfr[1] = sA[cur][k0 + tig + 4][p];
                mma_tf32(acc[0][nt], afr[0], bfr);
                mma_tf32(acc[1][nt], afr[1], bfr);
            }
        }
        if (hasnext) G1_STORE(cur ^ 1);
        __syncthreads();
        cur ^= 1;
    }
    // epilogue: +bias, store z, GN stats
    float s1[2] = {0.f, 0.f}, s2[2] = {0.f, 0.f};
    float* zb = g_z + (size_t)b * 128 * PSTR;
    #pragma unroll
    for (int mt = 0; mt < 2; mt++) {
        int o1 = obase + mt * 16 + gid;
        float bia = b1[o1], bib = b1[o1 + 8];
        #pragma unroll
        for (int nt = 0; nt < 8; nt++) {
            int p = p0 + pbase + nt * 8 + 2 * tig;
            float vx = acc[mt][nt].x + bia, vy = acc[mt][nt].y + bia;
            float vz = acc[mt][nt].z + bib, vw = acc[mt][nt].w + bib;
            if (fullA) {
                s1[mt] += vx + vy + vz + vw;
                s2[mt] += vx*vx + vy*vy + vz*vz + vw*vw;
                *(float2*)&zb[(size_t)o1 * PSTR + p] = make_float2(vx, vy);
                *(float2*)&zb[(size_t)(o1 + 8) * PSTR + p] = make_float2(vz, vw);
            } else {
                if (p < PP)     { zb[(size_t)o1*PSTR + p] = vx;       zb[(size_t)(o1+8)*PSTR + p] = vz;       s1[mt] += vx + vz; s2[mt] += vx*vx + vz*vz; }
                if (p + 1 < PP) { zb[(size_t)o1*PSTR + p + 1] = vy;   zb[(size_t)(o1+8)*PSTR + p + 1] = vw;   s1[mt] += vy + vw; s2[mt] += vy*vy + vw*vw; }
            }
        }
    }
    #pragma unroll
    for (int off = 16; off > 0; off >>= 1) {
        s1[0] += __shfl_down_sync(0xffffffffu, s1[0], off);
        s2[0] += __shfl_down_sync(0xffffffffu, s2[0], off);
        s1[1] += __shfl_down_sync(0xffffffffu, s1[1], off);
        s2[1] += __shfl_down_sync(0xffffffffu, s2[1], off);
    }
    if (lane == 0) {
        int g0 = (w >> 1) * 2;
        atomicAdd(&g_stats[(b * 8 + g0) * 2],     s1[0]);
        atomicAdd(&g_stats[(b * 8 + g0) * 2 + 1], s2[0]);
        atomicAdd(&g_stats[(b * 8 + g0 + 1) * 2],     s1[1]);
        atomicAdd(&g_stats[(b * 8 + g0 + 1) * 2 + 1], s2[1]);
    }
}

// ---------------- K4: finalize stats + gates (warp-parallel) ----------------
__global__ void k_small(const float* __restrict__ g1, const float* __restrict__ gb1,
                        const float* __restrict__ g2, const float* __restrict__ gb2) {
    int t = threadIdx.x;                       // 256 threads
    if (t < 64) {
        float s1 = g_stats[2 * t], s2 = g_stats[2 * t + 1];
        float invN = 1.f / (16.f * (float)PP);
        float mu = s1 * invN;
        float var = s2 * invN - mu * mu;
        g_munorm[2 * t] = mu;
        g_munorm[2 * t + 1] = rsqrtf(var + 1e-5f);
    }
    __shared__ float sh[8][16];
    int w = t >> 5, lane = t & 31;             // warp w -> batch w
    if (lane < 16) {
        float s = gb1[lane];
        #pragma unroll 4
        for (int c = 0; c < 64; c++) s += g_density[w * 64 + c] * g1[lane * 64 + c];
        sh[w][lane] = fmaxf(s, 0.f);
    }
    __syncwarp();
    if (lane < 4) {
        float s = gb2[lane];
        #pragma unroll
        for (int i = 0; i < 16; i++) s += sh[w][i] * g2[lane * 16 + i];
        g_gates[w * 4 + lane] = 1.f / (1.f + expf(-s));
    }
}

// ---------------- K5: gated = (gelu(GN(z)) @ w2^T + b2) * gate (tf32, pipelined) ----------------
__global__ void __launch_bounds__(256) k_gemm2(const float* __restrict__ w2,
                                               const float* __restrict__ b2,
                                               const float* __restrict__ gamma,
                                               const float* __restrict__ beta) {
    const int b = blockIdx.z;
    const int ob = blockIdx.y * 128;
    const int p0 = blockIdx.x * 128;
    __shared__ uint32_t sW[2][128][20];
    __shared__ uint32_t sA[2][16][136];
    __shared__ float sScale[128], sShift[128];
    const int tid = threadIdx.x;
    if (tid < 128) {
        int q = tid, g = q >> 4;
        float mu = g_munorm[(b * 8 + g) * 2];
        float rs = g_munorm[(b * 8 + g) * 2 + 1];
        float sc = rs * gamma[q];
        sScale[q] = sc;
        sShift[q] = beta[q] - mu * sc;
    }
    __syncthreads();
    const int w = tid >> 5, lane = tid & 31;
    const int gid = lane >> 2, tig = lane & 3;
    const int obase = (w >> 1) * 32, pbase = (w & 1) * 64;
    float4 acc[2][8] = {};
    const float* zb = g_z + (size_t)b * 128 * PSTR;
    const bool fullA = (p0 + 128 <= PP);

    const int ar0 = tid >> 5, ac0 = (tid & 31) * 4;
    const int wo0 = tid >> 2, wq0 = (tid & 3) * 4;
    float4 ra0, ra1, rw0, rw1;

    #define G2_LOAD(qc) do { \
        if (fullA) { \
            ra0 = *(const float4*)&zb[(size_t)((qc) + ar0) * PSTR + p0 + ac0]; \
            ra1 = *(const float4*)&zb[(size_t)((qc) + ar0 + 8) * PSTR + p0 + ac0]; \
        } else { \
            const float* r0p = &zb[(size_t)((qc) + ar0) * PSTR]; \
            const float* r1p = &zb[(size_t)((qc) + ar0 + 8) * PSTR]; \
            ra0.x = (p0+ac0   < PP) ? r0p[p0+ac0]   : 0.f; \
            ra0.y = (p0+ac0+1 < PP) ? r0p[p0+ac0+1] : 0.f; \
            ra0.z = (p0+ac0+2 < PP) ? r0p[p0+ac0+2] : 0.f; \
            ra0.w = (p0+ac0+3 < PP) ? r0p[p0+ac0+3] : 0.f; \
            ra1.x = (p0+ac0   < PP) ? r1p[p0+ac0]   : 0.f; \
            ra1.y = (p0+ac0+1 < PP) ? r1p[p0+ac0+1] : 0.f; \
            ra1.z = (p0+ac0+2 < PP) ? r1p[p0+ac0+2] : 0.f; \
            ra1.w = (p0+ac0+3 < PP) ? r1p[p0+ac0+3] : 0.f; \
        } \
        rw0 = *(const float4*)&w2[(ob + wo0) * 128 + (qc) + wq0]; \
        rw1 = *(const float4*)&w2[(ob + wo0 + 64) * 128 + (qc) + wq0]; \
    } while (0)
    #define GELU4(v, row) do { \
        float sc_ = sScale[row], sh_ = sShift[row]; \
        v.x = v.x * sc_ + sh_; v.x = 0.5f * v.x * (1.f + erff(v.x * 0.70710678118654752f)); \
        v.y = v.y * sc_ + sh_; v.y = 0.5f * v.y * (1.f + erff(v.y * 0.70710678118654752f)); \
        v.z = v.z * sc_ + sh_; v.z = 0.5f * v.z * (1.f + erff(v.z * 0.70710678118654752f)); \
        v.w = v.w * sc_ + sh_; v.w = 0.5f * v.w * (1.f + erff(v.w * 0.70710678118654752f)); \
    } while (0)
    #define G2_STORE(st, qc) do { \
        GELU4(ra0, (qc) + ar0); GELU4(ra1, (qc) + ar0 + 8); \
        *(uint4*)&sA[st][ar0][ac0]     = tf4(ra0); \
        *(uint4*)&sA[st][ar0 + 8][ac0] = tf4(ra1); \
        *(uint4*)&sW[st][wo0][wq0]       = tf4(rw0); \
        *(uint4*)&sW[st][wo0 + 64][wq0]  = tf4(rw1); \
    } while (0)

    G2_LOAD(0); G2_STORE(0, 0);
    __syncthreads();
    int cur = 0;
    for (int qc = 0; qc < 128; qc += 16) {
        const bool hasnext = (qc + 16 < 128);
        if (hasnext) G2_LOAD(qc + 16);
        #pragma unroll
        for (int ks = 0; ks < 2; ks++) {
            int k0 = ks * 8;
            uint32_t afr[2][4];
            #pragma unroll
            for (int mt = 0; mt < 2; mt++) {
                int o = obase + mt * 16 + gid;
                afr[mt][0] = sW[cur][o][k0 + tig];
                afr[mt][1] = sW[cur][o + 8][k0 + tig];
                afr[mt][2] = sW[cur][o][k0 + tig + 4];
                afr[mt][3] = sW[cur][o + 8][k0 + tig + 4];
            }
            #pragma unroll
            for (int nt = 0; nt < 8; nt++) {
                uint32_t bfr[2];
                int p = pbase + nt * 8 + gid;
                bfr[0] = sA[cur][k0 + tig][p];
                bfr[1] = sA[cur][k0 + tig + 4][p];
                mma_tf32(acc[0][nt], afr[0], bfr);
                mma_tf32(acc[1][nt], afr[1], bfr);
            }
        }
        if (hasnext) G2_STORE(cur ^ 1, qc + 16);
        __syncthreads();
        cur ^= 1;
    }
    float* gbuf = g_ff + (size_t)b * 256 * PSTR;
    #pragma unroll
    for (int mt = 0; mt < 2; mt++) {
        int o1 = ob + obase + mt * 16 + gid;
        float ga = g_gates[b * 4 + (o1 >> 6)];
        float gb_ = g_gates[b * 4 + ((o1 + 8) >> 6)];
        float bia = b2[o1], bib = b2[o1 + 8];
        #pragma unroll
        for (int nt = 0; nt < 8; nt++) {
            int p = p0 + pbase + nt * 8 + 2 * tig;
            float vx = (acc[mt][nt].x + bia) * ga, vy = (acc[mt][nt].y + bia) * ga;
            float vz = (acc[mt][nt].z + bib) * gb_, vw = (acc[mt][nt].w + bib) * gb_;
            if (fullA) {
                *(float2*)&gbuf[(size_t)o1 * PSTR + p] = make_float2(vx, vy);
                *(float2*)&gbuf[(size_t)(o1 + 8) * PSTR + p] = make_float2(vz, vw);
            } else {
                if (p < PP)     { gbuf[(size_t)o1*PSTR + p] = vx;     gbuf[(size_t)(o1+8)*PSTR + p] = vz; }
                if (p + 1 < PP) { gbuf[(size_t)o1*PSTR + p + 1] = vy; gbuf[(size_t)(o1+8)*PSTR + p + 1] = vw; }
            }
        }
    }
}

// ---------------- K6: IDWT2 -> g_recon ----------------
__global__ void __launch_bounds__(256) k_idwt() {
    int tile = blockIdx.x;         // 0..31 : 8 h-tiles x 4 w-tiles
    int bc = blockIdx.y;
    int h0 = (tile >> 2) * 32;
    int w0 = (tile & 3) * 64;
    int b = bc >> 6, c = bc & 63;
    __shared__ float scoef[4][19][36];
    __shared__ float stmp[4][19][68];
    const float* gb = g_ff + ((size_t)b * 256 + c) * PSTR;
    int ib0 = h0 >> 1, jb0 = w0 >> 1;

    for (int idx = threadIdx.x; idx < 4 * 19 * 35; idx += 256) {
        int k = idx / (19 * 35); int rem = idx % (19 * 35);
        int il = rem / 35, jl = rem % 35;
        scoef[k][il][jl] = gb[(size_t)k * 64 * PSTR + (ib0 + il) * OWW + jb0 + jl];
    }
    __syncthreads();
    for (int s = threadIdx.x; s < 19 * 16; s += 256) {
        int il = s >> 4, ws = s & 15;
        int wl = ws * 4, jb = wl >> 1;
        #pragma unroll
        for (int k = 0; k < 4; k++) {
            const float* fc = (k < 2) ? DEC_LO : DEC_HI;
            float c0 = scoef[k][il][jb],     c1 = scoef[k][il][jb + 1];
            float c2 = scoef[k][il][jb + 2], c3 = scoef[k][il][jb + 3];
            float c4 = scoef[k][il][jb + 4];
            stmp[k][il][wl + 0] = c0*fc[1] + c1*fc[3] + c2*fc[5] + c3*fc[7];
            stmp[k][il][wl + 1] = c0*fc[0] + c1*fc[2] + c2*fc[4] + c3*fc[6];
            stmp[k][il][wl + 2] = c1*fc[1] + c2*fc[3] + c3*fc[5] + c4*fc[7];
            stmp[k][il][wl + 3] = c1*fc[0] + c2*fc[2] + c3*fc[4] + c4*fc[6];
        }
    }
    __syncthreads();
    float* rb = g_recon + ((size_t)b * 64 + c) * HWSZ;
    for (int s = threadIdx.x; s < 512; s += 256) {
        int wlh = s & 63, hs = s >> 6;
        int hb = hs * 4, ib = hb >> 1;
        float t[4][5];
        #pragma unroll
        for (int k = 0; k < 4; k++)
            #pragma unroll
            for (int m = 0; m < 5; m++)
                t[k][m] = stmp[k][ib + m][wlh];
        #pragma unroll
        for (int dh = 0; dh < 4; dh++) {
            int sh = dh >> 1;
            float acc = 0.f;
            #pragma unroll
            for (int k = 0; k < 4; k++) {
                const float* fr = (k & 1) ? DEC_HI : DEC_LO;
                if (dh & 1)
                    acc += t[k][sh]*fr[0] + t[k][sh+1]*fr[2] + t[k][sh+2]*fr[4] + t[k][sh+3]*fr[6];
                else
                    acc += t[k][sh]*fr[1] + t[k][sh+1]*fr[3] + t[k][sh+2]*fr[5] + t[k][sh+3]*fr[7];
            }
            rb[(h0 + hb + dh) * WW + w0 + wlh] = acc;
        }
    }
}

// ---------------- K7: fused = [x, recon] @ wf^T + bf (tf32, pipelined) ----------------
__global__ void __launch_bounds__(256) k_final(const float* __restrict__ x,
                                               const float* __restrict__ wf,
                                               const float* __restrict__ bf,
                                               float* __restrict__ out) {
    const int b = blockIdx.y;
    const int p0 = blockIdx.x * 256;
    __shared__ uint32_t sW[2][64][20];
    __shared__ uint32_t sA[2][16][264];
    const int tid = threadIdx.x;
    const int w = tid >> 5, lane = tid & 31;
    const int gid = lane >> 2, tig = lane & 3;
    const int obase = (w >> 2) * 32, pbase = (w & 3) * 64;
    float4 acc[2][8] = {};
    const float* xb = x + (size_t)b * 64 * HWSZ;
    const float* rb = g_recon + (size_t)b * 64 * HWSZ;

    const int ar0 = tid >> 6;                 // base row, +4 per s
    const int ac0 = (tid & 63) * 4;
    const int wo0 = tid >> 2, wq0 = (tid & 3) * 4;
    float4 ra[4], rw0;

    #define G3_LOAD(cc) do { \
        _Pragma("unroll") \
        for (int s = 0; s < 4; s++) { \
            int ch = (cc) + ar0 + s * 4; \
            const float* src = (ch < 64) ? &xb[(size_t)ch * HWSZ] : &rb[(size_t)(ch - 64) * HWSZ]; \
            ra[s] = *(const float4*)&src[p0 + ac0]; \
        } \
        rw0 = *(const float4*)&wf[wo0 * 128 + (cc) + wq0]; \
    } while (0)
    #define G3_STORE(st) do { \
        _Pragma("unroll") \
        for (int s = 0; s < 4; s++) \
            *(uint4*)&sA[st][ar0 + s * 4][ac0] = tf4(ra[s]); \
        *(uint4*)&sW[st][wo0][wq0] = tf4(rw0); \
    } while (0)

    G3_LOAD(0); G3_STORE(0);
    __syncthreads();
    int cur = 0;
    for (int cc = 0; cc < 128; cc += 16) {
        const bool hasnext = (cc + 16 < 128);
        if (hasnext) G3_LOAD(cc + 16);
        #pragma unroll
        for (int ks = 0; ks < 2; ks++) {
            int k0 = ks * 8;
            uint32_t afr[2][4];
            #pragma unroll
            for (int mt = 0; mt < 2; mt++) {
                int o = obase + mt * 16 + gid;
                afr[mt][0] = sW[cur][o][k0 + tig];
                afr[mt][1] = sW[cur][o + 8][k0 + tig];
                afr[mt][2] = sW[cur][o][k0 + tig + 4];
                afr[mt][3] = sW[cur][o + 8][k0 + tig + 4];
            }
            #pragma unroll
            for (int nt = 0; nt < 8; nt++) {
                uint32_t bfr[2];
                int p = pbase + nt * 8 + gid;
                bfr[0] = sA[cur][k0 + tig][p];
                bfr[1] = sA[cur][k0 + tig + 4][p];
                mma_tf32(acc[0][nt], afr[0], bfr);
                mma_tf32(acc[1][nt], afr[1], bfr);
            }
        }
        if (hasnext) G3_STORE(cur ^ 1);
        __syncthreads();
        cur ^= 1;
    }
    float* ob = out + (size_t)b * 64 * HWSZ;
    #pragma unroll
    for (int mt = 0; mt < 2; mt++) {
        int o1 = obase + mt * 16 + gid;
        float bia = bf[o1], bib = bf[o1 + 8];
        #pragma unroll
        for (int nt = 0; nt < 8; nt++) {
            int p = p0 + pbase + nt * 8 + 2 * tig;
            *(float2*)&ob[(size_t)o1 * HWSZ + p] = make_float2(acc[mt][nt].x + bia, acc[mt][nt].y + bia);
            *(float2*)&ob[(size_t)(o1 + 8) * HWSZ + p] = make_float2(acc[mt][nt].z + bib, acc[mt][nt].w + bib);
        }
    }
}

extern "C" void kernel_launch(void* const* d_in, const int* in_sizes, int n_in,
                              void* d_out, int out_size) {
    const float* x     = (const float*)d_in[0];
    const float* w1    = (const float*)d_in[1];
    const float* b1    = (const float*)d_in[2];
    const float* gamma = (const float*)d_in[3];
    const float* beta  = (const float*)d_in[4];
    const float* w2    = (const float*)d_in[5];
    const float* b2    = (const float*)d_in[6];
    const float* g1    = (const float*)d_in[7];
    const float* gb1   = (const float*)d_in[8];
    const float* g2    = (const float*)d_in[9];
    const float* gb2   = (const float*)d_in[10];
    const float* wf    = (const float*)d_in[11];
    const float* bf    = (const float*)d_in[12];
    float* out = (float*)d_out;

    k_density<<<512, 256>>>(x);
    k_dwt<<<dim3(25, 512), 256>>>(x);
    k_gemm1<<<dim3(135, 8), 256>>>(w1, b1);
    k_small<<<1, 256>>>(g1, gb1, g2, gb2);
    k_gemm2<<<dim3(135, 2, 8), 256>>>(w2, b2, gamma, beta);
    k_idwt<<<dim3(32, 512), 256>>>();
    k_final<<<dim3(256, 8), 256>>>(x, wf, bf, out);
}

// round 5
// speedup vs baseline: 2.4577x; 1.1391x over previous
#include <cuda_runtime.h>
#include <stdint.h>
#include <math.h>

#define BB 8
#define CC 64
#define HH 256
#define WW 256
#define OHH 131
#define OWW 131
#define PP (OHH*OWW)      /* 17161 */
#define PSTR 17164        /* padded channel stride (multiple of 4) */
#define HWSZ (HH*WW)      /* 65536 */

// db4 filters
__constant__ float DEC_LO[8] = {
    -0.010597401784997278f, 0.032883011666982945f, 0.030841381835986965f,
    -0.18703481171888114f, -0.02798376941698385f, 0.6308807679295904f,
    0.7148465705525415f, 0.23037781330885523f };
__constant__ float DEC_HI[8] = {
    -0.23037781330885523f, 0.7148465705525415f, -0.6308807679295904f,
    -0.02798376941698385f, 0.18703481171888114f, 0.030841381835986965f,
    -0.032883011666982945f, -0.010597401784997278f };

// Scratch (device globals; allocation-free rule)
__device__ float g_ff[(size_t)BB*256*PSTR];    // ff then gated coeffs, (b, q=k*64+c, p)
__device__ float g_z[(size_t)BB*128*PSTR];     // z pre-GN, (b, o, p)
__device__ float g_recon[(size_t)BB*64*HWSZ];  // (b, c, h, w)
__device__ float g_stats[128];                 // (b,g): sum, sumsq
__device__ float g_density[512];
__device__ float g_munorm[128];                // (b,g): mu, rsig
__device__ float g_gates[32];                  // (b, k)

// ---- tf32 helpers ----
__device__ __forceinline__ uint32_t f2tf32(float x) {
    uint32_t r; asm("cvt.rna.tf32.f32 %0, %1;" : "=r"(r) : "f"(x)); return r;
}
__device__ __forceinline__ void mma_tf32(float4& d, const uint32_t a[4], const uint32_t b[2]) {
    asm volatile("mma.sync.aligned.m16n8k8.row.col.f32.tf32.tf32.f32 "
        "{%0,%1,%2,%3}, {%4,%5,%6,%7}, {%8,%9}, {%0,%1,%2,%3};"
        : "+f"(d.x), "+f"(d.y), "+f"(d.z), "+f"(d.w)
        : "r"(a[0]), "r"(a[1]), "r"(a[2]), "r"(a[3]), "r"(b[0]), "r"(b[1]));
}
__device__ __forceinline__ uint4 tf4(float4 v) {
    uint4 u; u.x = f2tf32(v.x); u.y = f2tf32(v.y); u.z = f2tf32(v.z); u.w = f2tf32(v.w);
    return u;
}

// ---------------- K1: density + zero stats ----------------
__global__ void k_density(const float* __restrict__ x) {
    int bc = blockIdx.x;
    const float4* xp = (const float4*)(x + (size_t)bc * HWSZ);
    int cnt = 0;
    for (int i = threadIdx.x; i < HWSZ/4; i += 256) {
        float4 v = xp[i];
        cnt += (v.x != 0.f) + (v.y != 0.f) + (v.z != 0.f) + (v.w != 0.f);
    }
    __shared__ int red[256];
    red[threadIdx.x] = cnt; __syncthreads();
    for (int s = 128; s > 0; s >>= 1) {
        if (threadIdx.x < s) red[threadIdx.x] += red[threadIdx.x + s];
        __syncthreads();
    }
    if (threadIdx.x == 0) g_density[bc] = (float)red[0] / (float)HWSZ;
    if (blockIdx.x == 0 && threadIdx.x < 128) g_stats[threadIdx.x] = 0.f;
}

// ---------------- K2: DWT2 -> g_ff (full-width row bands) ----------------
// block = (hband 0..16, bc). 8 output rows x 131 cols per block.
// sIn col layout: orig col n lives at index n+8 (reflect-filled edges).
__global__ void __launch_bounds__(256) k_dwt(const float* __restrict__ x) {
    const int gi0 = blockIdx.x * 8;
    const int bc = blockIdx.y;
    __shared__ float sIn[22][272];
    __shared__ float sT[2][22][132];
    const float* xp = x + (size_t)bc * HWSZ;

    // bulk rows: xe rows 2gi0..2gi0+21 -> orig m = 2gi0-6+r (reflect)
    for (int idx = threadIdx.x; idx < 22 * 64; idx += 256) {
        int r = idx >> 6, q = idx & 63;
        int m = 2 * gi0 - 6 + r;
        m = (m < 0) ? (-1 - m) : ((m > 255) ? (511 - m) : m);
        float4 v = *(const float4*)&xp[m * 256 + 4 * q];
        *(float4*)&sIn[r][8 + 4 * q] = v;
    }
    // edge cols: e<6: col 2+e <-> orig n=e-6 -> reflect 5-e ; e>=6: col 258+e <-> orig 250+e -> 261-e
    for (int idx = threadIdx.x; idx < 22 * 12; idx += 256) {
        int r = idx / 12, e = idx % 12;
        int m = 2 * gi0 - 6 + r;
        m = (m < 0) ? (-1 - m) : ((m > 255) ? (511 - m) : m);
        int col = (e < 6) ? (2 + e) : (258 + e);
        int n = (e < 6) ? (5 - e) : (261 - e);
        sIn[r][col] = xp[m * 256 + n];
    }
    __syncthreads();
    // row pass: 22 rows x 131 cols
    for (int idx = threadIdx.x; idx < 22 * 131; idx += 256) {
        int r = idx / 131, j = idx % 131;
        float lo = 0.f, hi = 0.f;
        #pragma unroll
        for (int v = 0; v < 8; v++) {
            float xv = sIn[r][2 * j + v + 2];
            lo += xv * DEC_LO[7 - v];
            hi += xv * DEC_HI[7 - v];
        }
        sT[0][r][j] = lo; sT[1][r][j] = hi;
    }
    __syncthreads();
    int b = bc >> 6, c = bc & 63;
    float* base = g_ff + ((size_t)b * 256 + c) * PSTR;
    for (int idx = threadIdx.x; idx < 8 * 131; idx += 256) {
        int ii = idx / 131, j = idx % 131;
        int gi = gi0 + ii;
        if (gi < OHH) {
            float aa = 0.f, da = 0.f, ad = 0.f, dd = 0.f;
            #pragma unroll
            for (int u = 0; u < 8; u++) {
                float tl = sT[0][2 * ii + u][j], th = sT[1][2 * ii + u][j];
                float gl = DEC_LO[7 - u], gh = DEC_HI[7 - u];
                aa += gl * tl; da += gh * tl; ad += gl * th; dd += gh * th;
            }
            int p = gi * OWW + j;
            base[p] = aa;
            base[(size_t)64 * PSTR + p] = da;
            base[(size_t)128 * PSTR + p] = ad;
            base[(size_t)192 * PSTR + p] = dd;
        }
    }
}

// ---------------- K3: z = ff @ w1^T + b1, + GN stats (tf32 tensor, pipelined) ----------------
__global__ void __launch_bounds__(256) k_gemm1(const float* __restrict__ w1,
                                               const float* __restrict__ b1) {
    const int b = blockIdx.y;
    const int p0 = blockIdx.x * 128;
    __shared__ uint32_t sW[2][128][20];
    __shared__ uint32_t sA[2][16][136];
    const int tid = threadIdx.x;
    const int w = tid >> 5, lane = tid & 31;
    const int gid = lane >> 2, tig = lane & 3;
    const int obase = (w >> 1) * 32, pbase = (w & 1) * 64;
    float4 acc[2][8] = {};
    const float* ffb = g_ff + (size_t)b * 256 * PSTR;
    const bool fullA = (p0 + 128 <= PP);

    const int ar0 = tid >> 5, ac0 = (tid & 31) * 4;
    const int wo0 = tid >> 2, wq0 = (tid & 3) * 4;
    float4 ra0, ra1, rw0, rw1;

    #define G1_LOAD(qc) do { \
        if (fullA) { \
            ra0 = *(const float4*)&ffb[(size_t)((qc) + ar0) * PSTR + p0 + ac0]; \
            ra1 = *(const float4*)&ffb[(size_t)((qc) + ar0 + 8) * PSTR + p0 + ac0]; \
        } else { \
            const float* r0p = &ffb[(size_t)((qc) + ar0) * PSTR]; \
            const float* r1p = &ffb[(size_t)((qc) + ar0 + 8) * PSTR]; \
            ra0.x = (p0+ac0   < PP) ? r0p[p0+ac0]   : 0.f; \
            ra0.y = (p0+ac0+1 < PP) ? r0p[p0+ac0+1] : 0.f; \
            ra0.z = (p0+ac0+2 < PP) ? r0p[p0+ac0+2] : 0.f; \
            ra0.w = (p0+ac0+3 < PP) ? r0p[p0+ac0+3] : 0.f; \
            ra1.x = (p0+ac0   < PP) ? r1p[p0+ac0]   : 0.f; \
            ra1.y = (p0+ac0+1 < PP) ? r1p[p0+ac0+1] : 0.f; \
            ra1.z = (p0+ac0+2 < PP) ? r1p[p0+ac0+2] : 0.f; \
            ra1.w = (p0+ac0+3 < PP) ? r1p[p0+ac0+3] : 0.f; \
        } \
        rw0 = *(const float4*)&w1[wo0 * 256 + (qc) + wq0]; \
        rw1 = *(const float4*)&w1[(wo0 + 64) * 256 + (qc) + wq0]; \
    } while (0)
    #define G1_STORE(st) do { \
        *(uint4*)&sA[st][ar0][ac0]     = tf4(ra0); \
        *(uint4*)&sA[st][ar0 + 8][ac0] = tf4(ra1); \
        *(uint4*)&sW[st][wo0][wq0]       = tf4(rw0); \
        *(uint4*)&sW[st][wo0 + 64][wq0]  = tf4(rw1); \
    } while (0)

    G1_LOAD(0); G1_STORE(0);
    __syncthreads();
    int cur = 0;
    for (int qc = 0; qc < 256; qc += 16) {
        const bool hasnext = (qc + 16 < 256);
        if (hasnext) G1_LOAD(qc + 16);
        #pragma unroll
        for (int ks = 0; ks < 2; ks++) {
            int k0 = ks * 8;
            uint32_t afr[2][4];
            #pragma unroll
            for (int mt = 0; mt < 2; mt++) {
                int o = obase + mt * 16 + gid;
                afr[mt][0] = sW[cur][o][k0 + tig];
                afr[mt][1] = sW[cur][o + 8][k0 + tig];
                afr[mt][2] = sW[cur][o][k0 + tig + 4];
                afr[mt][3] = sW[cur][o + 8][k0 + tig + 4];
            }
            #pragma unroll
            for (int nt = 0; nt < 8; nt++) {
                uint32_t bfr[2];
                int p = pbase + nt * 8 + gid;
                bfr[0] = sA[cur][k0 + tig][p];
                bfr[1] = sA[cur][k0 + tig + 4][p];
                mma_tf32(acc[0][nt], afr[0], bfr);
                mma_tf32(acc[1][nt], afr[1], bfr);
            }
        }
        if (hasnext) G1_STORE(cur ^ 1);
        __syncthreads();
        cur ^= 1;
    }
    float s1[2] = {0.f, 0.f}, s2[2] = {0.f, 0.f};
    float* zb = g_z + (size_t)b * 128 * PSTR;
    #pragma unroll
    for (int mt = 0; mt < 2; mt++) {
        int o1 = obase + mt * 16 + gid;
        float bia = b1[o1], bib = b1[o1 + 8];
        #pragma unroll
        for (int nt = 0; nt < 8; nt++) {
            int p = p0 + pbase + nt * 8 + 2 * tig;
            float vx = acc[mt][nt].x + bia, vy = acc[mt][nt].y + bia;
            float vz = acc[mt][nt].z + bib, vw = acc[mt][nt].w + bib;
            if (fullA) {
                s1[mt] += vx + vy + vz + vw;
                s2[mt] += vx*vx + vy*vy + vz*vz + vw*vw;
                *(float2*)&zb[(size_t)o1 * PSTR + p] = make_float2(vx, vy);
                *(float2*)&zb[(size_t)(o1 + 8) * PSTR + p] = make_float2(vz, vw);
            } else {
                if (p < PP)     { zb[(size_t)o1*PSTR + p] = vx;       zb[(size_t)(o1+8)*PSTR + p] = vz;       s1[mt] += vx + vz; s2[mt] += vx*vx + vz*vz; }
                if (p + 1 < PP) { zb[(size_t)o1*PSTR + p + 1] = vy;   zb[(size_t)(o1+8)*PSTR + p + 1] = vw;   s1[mt] += vy + vw; s2[mt] += vy*vy + vw*vw; }
            }
        }
    }
    #pragma unroll
    for (int off = 16; off > 0; off >>= 1) {
        s1[0] += __shfl_down_sync(0xffffffffu, s1[0], off);
        s2[0] += __shfl_down_sync(0xffffffffu, s2[0], off);
        s1[1] += __shfl_down_sync(0xffffffffu, s1[1], off);
        s2[1] += __shfl_down_sync(0xffffffffu, s2[1], off);
    }
    if (lane == 0) {
        int g0 = (w >> 1) * 2;
        atomicAdd(&g_stats[(b * 8 + g0) * 2],     s1[0]);
        atomicAdd(&g_stats[(b * 8 + g0) * 2 + 1], s2[0]);
        atomicAdd(&g_stats[(b * 8 + g0 + 1) * 2],     s1[1]);
        atomicAdd(&g_stats[(b * 8 + g0 + 1) * 2 + 1], s2[1]);
    }
}

// ---------------- K4: finalize stats + gates (warp-parallel) ----------------
__global__ void k_small(const float* __restrict__ g1, const float* __restrict__ gb1,
                        const float* __restrict__ g2, const float* __restrict__ gb2) {
    int t = threadIdx.x;
    if (t < 64) {
        float s1 = g_stats[2 * t], s2 = g_stats[2 * t + 1];
        float invN = 1.f / (16.f * (float)PP);
        float mu = s1 * invN;
        float var = s2 * invN - mu * mu;
        g_munorm[2 * t] = mu;
        g_munorm[2 * t + 1] = rsqrtf(var + 1e-5f);
    }
    __shared__ float sh[8][16];
    int w = t >> 5, lane = t & 31;
    if (lane < 16) {
        float s = gb1[lane];
        #pragma unroll 4
        for (int c = 0; c < 64; c++) s += g_density[w * 64 + c] * g1[lane * 64 + c];
        sh[w][lane] = fmaxf(s, 0.f);
    }
    __syncwarp();
    if (lane < 4) {
        float s = gb2[lane];
        #pragma unroll
        for (int i = 0; i < 16; i++) s += sh[w][i] * g2[lane * 16 + i];
        g_gates[w * 4 + lane] = 1.f / (1.f + expf(-s));
    }
}

// ---------------- K5: gated = (gelu(GN(z)) @ w2^T + b2) * gate ----------------
// M=256 (all outputs per block), N=64 px. Single z read, single GELU per element.
__global__ void __launch_bounds__(256) k_gemm2(const float* __restrict__ w2,
                                               const float* __restrict__ b2,
                                               const float* __restrict__ gamma,
                                               const float* __restrict__ beta) {
    const int b = blockIdx.y;
    const int p0 = blockIdx.x * 64;
    __shared__ uint32_t sWt[2][16][260];   // K-major W tile
    __shared__ uint32_t sA[2][16][72];
    __shared__ float sScale[128], sShift[128];
    const int tid = threadIdx.x;
    if (tid < 128) {
        int q = tid, g = q >> 4;
        float mu = g_munorm[(b * 8 + g) * 2];
        float rs = g_munorm[(b * 8 + g) * 2 + 1];
        float sc = rs * gamma[q];
        sScale[q] = sc;
        sShift[q] = beta[q] - mu * sc;
    }
    __syncthreads();
    const int w = tid >> 5, lane = tid & 31;
    const int gid = lane >> 2, tig = lane & 3;
    const int obase = (w >> 1) * 64, pbase = (w & 1) * 32;
    float4 acc[4][4] = {};
    const float* zb = g_z + (size_t)b * 128 * PSTR;
    const bool fullA = (p0 + 64 <= PP);

    const int ar = tid >> 4, ac = (tid & 15) * 4;   // A: 16 rows x 64 px
    const int wo = tid >> 2, wq = (tid & 3) * 4;    // W: 64 o x 4 q per thread set, x4 sets
    float4 ra, rw[4];

    #define G2_LOAD(qc) do { \
        if (fullA) { \
            ra = *(const float4*)&zb[(size_t)((qc) + ar) * PSTR + p0 + ac]; \
        } else { \
            const float* rp = &zb[(size_t)((qc) + ar) * PSTR]; \
            ra.x = (p0+ac   < PP) ? rp[p0+ac]   : 0.f; \
            ra.y = (p0+ac+1 < PP) ? rp[p0+ac+1] : 0.f; \
            ra.z = (p0+ac+2 < PP) ? rp[p0+ac+2] : 0.f; \
            ra.w = (p0+ac+3 < PP) ? rp[p0+ac+3] : 0.f; \
        } \
        _Pragma("unroll") \
        for (int s = 0; s < 4; s++) \
            rw[s] = *(const float4*)&w2[(wo + s * 64) * 128 + (qc) + wq]; \
    } while (0)
    #define GELU4(v, row) do { \
        float sc_ = sScale[row], sh_ = sShift[row]; \
        v.x = v.x * sc_ + sh_; v.x = 0.5f * v.x * (1.f + erff(v.x * 0.70710678118654752f)); \
        v.y = v.y * sc_ + sh_; v.y = 0.5f * v.y * (1.f + erff(v.y * 0.70710678118654752f)); \
        v.z = v.z * sc_ + sh_; v.z = 0.5f * v.z * (1.f + erff(v.z * 0.70710678118654752f)); \
        v.w = v.w * sc_ + sh_; v.w = 0.5f * v.w * (1.f + erff(v.w * 0.70710678118654752f)); \
    } while (0)
    #define G2_STORE(st, qc) do { \
        GELU4(ra, (qc) + ar); \
        *(uint4*)&sA[st][ar][ac] = tf4(ra); \
        _Pragma("unroll") \
        for (int s = 0; s < 4; s++) { \
            sWt[st][wq + 0][wo + s * 64] = f2tf32(rw[s].x); \
            sWt[st][wq + 1][wo + s * 64] = f2tf32(rw[s].y); \
            sWt[st][wq + 2][wo + s * 64] = f2tf32(rw[s].z); \
            sWt[st][wq + 3][wo + s * 64] = f2tf32(rw[s].w); \
        } \
    } while (0)

    G2_LOAD(0); G2_STORE(0, 0);
    __syncthreads();
    int cur = 0;
    for (int qc = 0; qc < 128; qc += 16) {
        const bool hasnext = (qc + 16 < 128);
        if (hasnext) G2_LOAD(qc + 16);
        #pragma unroll
        for (int ks = 0; ks < 2; ks++) {
            int k0 = ks * 8;
            uint32_t afr[4][4];
            #pragma unroll
            for (int mt = 0; mt < 4; mt++) {
                int o = obase + mt * 16 + gid;
                afr[mt][0] = sWt[cur][k0 + tig][o];
                afr[mt][1] = sWt[cur][k0 + tig][o + 8];
                afr[mt][2] = sWt[cur][k0 + tig + 4][o];
                afr[mt][3] = sWt[cur][k0 + tig + 4][o + 8];
            }
            #pragma unroll
            for (int nt = 0; nt < 4; nt++) {
                uint32_t bfr[2];
                int p = pbase + nt * 8 + gid;
                bfr[0] = sA[cur][k0 + tig][p];
                bfr[1] = sA[cur][k0 + tig + 4][p];
                #pragma unroll
                for (int mt = 0; mt < 4; mt++)
                    mma_tf32(acc[mt][nt], afr[mt], bfr);
            }
        }
        if (hasnext) G2_STORE(cur ^ 1, qc + 16);
        __syncthreads();
        cur ^= 1;
    }
    float* gbuf = g_ff + (size_t)b * 256 * PSTR;
    #pragma unroll
    for (int mt = 0; mt < 4; mt++) {
        int o1 = obase + mt * 16 + gid;
        float ga = g_gates[b * 4 + (o1 >> 6)];
        float gb_ = g_gates[b * 4 + ((o1 + 8) >> 6)];
        float bia = b2[o1], bib = b2[o1 + 8];
        #pragma unroll
        for (int nt = 0; nt < 4; nt++) {
            int p = p0 + pbase + nt * 8 + 2 * tig;
            float vx = (acc[mt][nt].x + bia) * ga, vy = (acc[mt][nt].y + bia) * ga;
            float vz = (acc[mt][nt].z + bib) * gb_, vw = (acc[mt][nt].w + bib) * gb_;
            if (fullA) {
                *(float2*)&gbuf[(size_t)o1 * PSTR + p] = make_float2(vx, vy);
                *(float2*)&gbuf[(size_t)(o1 + 8) * PSTR + p] = make_float2(vz, vw);
            } else {
                if (p < PP)     { gbuf[(size_t)o1*PSTR + p] = vx;     gbuf[(size_t)(o1+8)*PSTR + p] = vz; }
                if (p + 1 < PP) { gbuf[(size_t)o1*PSTR + p + 1] = vy; gbuf[(size_t)(o1+8)*PSTR + p + 1] = vw; }
            }
        }
    }
}

// ---------------- K6: IDWT2 -> g_recon ----------------
__global__ void __launch_bounds__(256) k_idwt() {
    int tile = blockIdx.x;         // 0..31 : 8 h-tiles x 4 w-tiles
    int bc = blockIdx.y;
    int h0 = (tile >> 2) * 32;
    int w0 = (tile & 3) * 64;
    int b = bc >> 6, c = bc & 63;
    __shared__ float scoef[4][19][36];
    __shared__ float stmp[4][19][68];
    const float* gb = g_ff + ((size_t)b * 256 + c) * PSTR;
    int ib0 = h0 >> 1, jb0 = w0 >> 1;

    for (int idx = threadIdx.x; idx < 4 * 19 * 35; idx += 256) {
        int k = idx / (19 * 35); int rem = idx % (19 * 35);
        int il = rem / 35, jl = rem % 35;
        scoef[k][il][jl] = gb[(size_t)k * 64 * PSTR + (ib0 + il) * OWW + jb0 + jl];
    }
    __syncthreads();
    for (int s = threadIdx.x; s < 19 * 16; s += 256) {
        int il = s >> 4, ws = s & 15;
        int wl = ws * 4, jb = wl >> 1;
        #pragma unroll
        for (int k = 0; k < 4; k++) {
            const float* fc = (k < 2) ? DEC_LO : DEC_HI;
            float c0 = scoef[k][il][jb],     c1 = scoef[k][il][jb + 1];
            float c2 = scoef[k][il][jb + 2], c3 = scoef[k][il][jb + 3];
            float c4 = scoef[k][il][jb + 4];
            stmp[k][il][wl + 0] = c0*fc[1] + c1*fc[3] + c2*fc[5] + c3*fc[7];
            stmp[k][il][wl + 1] = c0*fc[0] + c1*fc[2] + c2*fc[4] + c3*fc[6];
            stmp[k][il][wl + 2] = c1*fc[1] + c2*fc[3] + c3*fc[5] + c4*fc[7];
            stmp[k][il][wl + 3] = c1*fc[0] + c2*fc[2] + c3*fc[4] + c4*fc[6];
        }
    }
    __syncthreads();
    float* rb = g_recon + ((size_t)b * 64 + c) * HWSZ;
    for (int s = threadIdx.x; s < 512; s += 256) {
        int wlh = s & 63, hs = s >> 6;
        int hb = hs * 4, ib = hb >> 1;
        float t[4][5];
        #pragma unroll
        for (int k = 0; k < 4; k++)
            #pragma unroll
            for (int m = 0; m < 5; m++)
                t[k][m] = stmp[k][ib + m][wlh];
        #pragma unroll
        for (int dh = 0; dh < 4; dh++) {
            int sh = dh >> 1;
            float acc = 0.f;
            #pragma unroll
            for (int k = 0; k < 4; k++) {
                const float* fr = (k & 1) ? DEC_HI : DEC_LO;
                if (dh & 1)
                    acc += t[k][sh]*fr[0] + t[k][sh+1]*fr[2] + t[k][sh+2]*fr[4] + t[k][sh+3]*fr[6];
                else
                    acc += t[k][sh]*fr[1] + t[k][sh+1]*fr[3] + t[k][sh+2]*fr[5] + t[k][sh+3]*fr[7];
            }
            rb[(h0 + hb + dh) * WW + w0 + wlh] = acc;
        }
    }
}

// ---------------- K7: fused = [x, recon] @ wf^T + bf (tf32, pipelined) ----------------
__global__ void __launch_bounds__(256) k_final(const float* __restrict__ x,
                                               const float* __restrict__ wf,
                                               const float* __restrict__ bf,
                                               float* __restrict__ out) {
    const int b = blockIdx.y;
    const int p0 = blockIdx.x * 256;
    __shared__ uint32_t sW[2][64][20];
    __shared__ uint32_t sA[2][16][264];
    const int tid = threadIdx.x;
    const int w = tid >> 5, lane = tid & 31;
    const int gid = lane >> 2, tig = lane & 3;
    const int obase = (w >> 2) * 32, pbase = (w & 3) * 64;
    float4 acc[2][8] = {};
    const float* xb = x + (size_t)b * 64 * HWSZ;
    const float* rb = g_recon + (size_t)b * 64 * HWSZ;

    const int ar0 = tid >> 6;
    const int ac0 = (tid & 63) * 4;
    const int wo0 = tid >> 2, wq0 = (tid & 3) * 4;
    float4 ra[4], rw0;

    #define G3_LOAD(cc) do { \
        _Pragma("unroll") \
        for (int s = 0; s < 4; s++) { \
            int ch = (cc) + ar0 + s * 4; \
            const float* src = (ch < 64) ? &xb[(size_t)ch * HWSZ] : &rb[(size_t)(ch - 64) * HWSZ]; \
            ra[s] = *(const float4*)&src[p0 + ac0]; \
        } \
        rw0 = *(const float4*)&wf[wo0 * 128 + (cc) + wq0]; \
    } while (0)
    #define G3_STORE(st) do { \
        _Pragma("unroll") \
        for (int s = 0; s < 4; s++) \
            *(uint4*)&sA[st][ar0 + s * 4][ac0] = tf4(ra[s]); \
        *(uint4*)&sW[st][wo0][wq0] = tf4(rw0); \
    } while (0)

    G3_LOAD(0); G3_STORE(0);
    __syncthreads();
    int cur = 0;
    for (int cc = 0; cc < 128; cc += 16) {
        const bool hasnext = (cc + 16 < 128);
        if (hasnext) G3_LOAD(cc + 16);
        #pragma unroll
        for (int ks = 0; ks < 2; ks++) {
            int k0 = ks * 8;
            uint32_t afr[2][4];
            #pragma unroll
            for (int mt = 0; mt < 2; mt++) {
                int o = obase + mt * 16 + gid;
                afr[mt][0] = sW[cur][o][k0 + tig];
                afr[mt][1] = sW[cur][o + 8][k0 + tig];
                afr[mt][2] = sW[cur][o][k0 + tig + 4];
                afr[mt][3] = sW[cur][o + 8][k0 + tig + 4];
            }
            #pragma unroll
            for (int nt = 0; nt < 8; nt++) {
                uint32_t bfr[2];
                int p = pbase + nt * 8 + gid;
                bfr[0] = sA[cur][k0 + tig][p];
                bfr[1] = sA[cur][k0 + tig + 4][p];
                mma_tf32(acc[0][nt], afr[0], bfr);
                mma_tf32(acc[1][nt], afr[1], bfr);
            }
        }
        if (hasnext) G3_STORE(cur ^ 1);
        __syncthreads();
        cur ^= 1;
    }
    float* ob = out + (size_t)b * 64 * HWSZ;
    #pragma unroll
    for (int mt = 0; mt < 2; mt++) {
        int o1 = obase + mt * 16 + gid;
        float bia = bf[o1], bib = bf[o1 + 8];
        #pragma unroll
        for (int nt = 0; nt < 8; nt++) {
            int p = p0 + pbase + nt * 8 + 2 * tig;
            *(float2*)&ob[(size_t)o1 * HWSZ + p] = make_float2(acc[mt][nt].x + bia, acc[mt][nt].y + bia);
            *(float2*)&ob[(size_t)(o1 + 8) * HWSZ + p] = make_float2(acc[mt][nt].z + bib, acc[mt][nt].w + bib);
        }
    }
}

extern "C" void kernel_launch(void* const* d_in, const int* in_sizes, int n_in,
                              void* d_out, int out_size) {
    const float* x     = (const float*)d_in[0];
    const float* w1    = (const float*)d_in[1];
    const float* b1    = (const float*)d_in[2];
    const float* gamma = (const float*)d_in[3];
    const float* beta  = (const float*)d_in[4];
    const float* w2    = (const float*)d_in[5];
    const float* b2    = (const float*)d_in[6];
    const float* g1    = (const float*)d_in[7];
    const float* gb1   = (const float*)d_in[8];
    const float* g2    = (const float*)d_in[9];
    const float* gb2   = (const float*)d_in[10];
    const float* wf    = (const float*)d_in[11];
    const float* bf    = (const float*)d_in[12];
    float* out = (float*)d_out;

    k_density<<<512, 256>>>(x);
    k_dwt<<<dim3(17, 512), 256>>>(x);
    k_gemm1<<<dim3(135, 8), 256>>>(w1, b1);
    k_small<<<1, 256>>>(g1, gb1, g2, gb2);
    k_gemm2<<<dim3(269, 8), 256>>>(w2, b2, gamma, beta);
    k_idwt<<<dim3(32, 512), 256>>>();
    k_final<<<dim3(256, 8), 256>>>(x, wf, bf, out);
}